// round 14
// baseline (speedup 1.0000x reference)
#include <cuda_runtime.h>
#include <cuda_bf16.h>
#include <cuda_fp16.h>
#include <math.h>
#include <stdint.h>

#define NB 16
#define LL 1024
#define HH 768
#define OUTW (4*HH)
#define KCP (HH/32)   // 24 hi/lo k32-chunks for proj/scores operands
#define KCS (LL/64)   // 16 fp16 k64-chunks (max) for att operands
#define KVS (LL/64)

// ---------------------------------------------------------------------------
// Packed scratch
// ---------------------------------------------------------------------------
__device__ uint4 g_x1p[(size_t)NB*LL*KCP*8];   // 48 MB hi/lo
__device__ uint4 g_x2p[(size_t)NB*LL*KCP*8];   // 48 MB hi/lo (COMPACT rows)
__device__ uint4 g_wp [(size_t)HH*KCP*8];      // 2.25 MB hi/lo
__device__ uint4 g_xpp[(size_t)NB*LL*KCP*8];   // 48 MB hi/lo
__device__ uint4 g_ypp[(size_t)NB*LL*KCP*8];   // 48 MB hi/lo (COMPACT rows)
__device__ uint4 g_ap [(size_t)NB*LL*KCS*8];   // 32 MB fp16 alpha (compact j')
__device__ uint4 g_vtp[(size_t)NB*HH*KVS*8];   // 24 MB fp16 x2^T (compact j')
__device__ float g_sc [(size_t)NB*LL*LL];      // 64 MB scores fp32 (compact cols)
__device__ int   g_jidx[NB][LL];               // compacted j index per batch
__device__ int   g_cnt [NB];                   // unmasked count per batch

// ---------------------------------------------------------------------------
__device__ __forceinline__ uint32_t smem_u32(const void* p) {
    uint32_t a;
    asm("{ .reg .u64 t; cvta.to.shared.u64 t, %1; cvt.u32.u64 %0, t; }"
        : "=r"(a) : "l"(p));
    return a;
}

__device__ __forceinline__ void split4(float4 v, uint32_t& h0, uint32_t& h1,
                                       uint32_t& l0, uint32_t& l1) {
    __nv_bfloat162 a = __floats2bfloat162_rn(v.x, v.y);
    __nv_bfloat162 b = __floats2bfloat162_rn(v.z, v.w);
    float2 fa = __bfloat1622float2(a), fb = __bfloat1622float2(b);
    __nv_bfloat162 c = __floats2bfloat162_rn(v.x - fa.x, v.y - fa.y);
    __nv_bfloat162 d = __floats2bfloat162_rn(v.z - fb.x, v.w - fb.y);
    h0 = *reinterpret_cast<uint32_t*>(&a);
    h1 = *reinterpret_cast<uint32_t*>(&b);
    l0 = *reinterpret_cast<uint32_t*>(&c);
    l1 = *reinterpret_cast<uint32_t*>(&d);
}

#define CP16(dst, src) \
    asm volatile("cp.async.cg.shared.global [%0], [%1], 16;" :: "r"(dst), "l"(src))
#define CPCOMMIT() asm volatile("cp.async.commit_group;" ::: "memory")
#define CPWAIT1()  asm volatile("cp.async.wait_group 1;" ::: "memory")

#define LDSM4(r0,r1,r2,r3,addr) \
    asm volatile("ldmatrix.sync.aligned.m8n8.x4.shared.b16 {%0,%1,%2,%3}, [%4];" \
                 : "=r"(r0),"=r"(r1),"=r"(r2),"=r"(r3) : "r"(addr))

#define MMA(c,a0,a1,a2,a3,b0,b1) \
    asm volatile("mma.sync.aligned.m16n8k16.row.col.f32.bf16.bf16.f32 " \
                 "{%0,%1,%2,%3}, {%4,%5,%6,%7}, {%8,%9}, {%0,%1,%2,%3};" \
                 : "+f"((c)[0]),"+f"((c)[1]),"+f"((c)[2]),"+f"((c)[3]) \
                 : "r"(a0),"r"(a1),"r"(a2),"r"(a3),"r"(b0),"r"(b1))

#define MMA_H(c,a0,a1,a2,a3,b0,b1) \
    asm volatile("mma.sync.aligned.m16n8k16.row.col.f32.f16.f16.f32 " \
                 "{%0,%1,%2,%3}, {%4,%5,%6,%7}, {%8,%9}, {%0,%1,%2,%3};" \
                 : "+f"((c)[0]),"+f"((c)[1]),"+f"((c)[2]),"+f"((c)[3]) \
                 : "r"(a0),"r"(a1),"r"(a2),"r"(a3),"r"(b0),"r"(b1))

// CTA tile 128x64: stage = A 16KB + B 8KB
#define STAGE_BYTES 24576u
#define SMEM_BYTES  (3 * 24576)

// ---------------------------------------------------------------------------
// 3-pass split-bf16 mainloop. a_tsrc = THIS thread's A source (row + seg resolved).
// ---------------------------------------------------------------------------
__device__ __forceinline__ void gemm_main3(const uint8_t* __restrict__ a_tsrc,
                                           const uint8_t* __restrict__ Bp,
                                           int KC, char* smem, float (&c)[2][4][4])
{
    const int tid  = threadIdx.x;
    const int lane = tid & 31, wid = tid >> 5;
    const int wm = wid >> 1, wn = wid & 1;
    const uint32_t sb = smem_u32(smem);

    #pragma unroll
    for (int mi = 0; mi < 2; mi++)
        #pragma unroll
        for (int ni = 0; ni < 4; ni++)
            #pragma unroll
            for (int q = 0; q < 4; q++) c[mi][ni][q] = 0.f;

    const int ar = tid >> 1;
    const int as = (tid & 1) * 4;
    uint32_t dswA[4];
    #pragma unroll
    for (int i = 0; i < 4; i++)
        dswA[i] = (uint32_t)(ar * 128 + (((as + i) * 16) ^ ((ar & 7) << 4)));
    const int br = tid >> 2;
    const int bs = (tid & 3) * 2;
    const uint8_t* bsrc = Bp + (size_t)br * KC * 128 + bs * 16;
    uint32_t dswB[2];
    #pragma unroll
    for (int i = 0; i < 2; i++)
        dswB[i] = (uint32_t)(br * 128 + (((bs + i) * 16) ^ ((br & 7) << 4)));

    auto issue = [&](int kt, int st) {
        const uint32_t base = sb + (uint32_t)st * STAGE_BYTES;
        const uint8_t* a = a_tsrc + (size_t)kt * 128;
        const uint8_t* b = bsrc + (size_t)kt * 128;
        #pragma unroll
        for (int i = 0; i < 4; i++) CP16(base + dswA[i], a + i * 16);
        #pragma unroll
        for (int i = 0; i < 2; i++) CP16(base + 16384u + dswB[i], b + i * 16);
    };

    issue(0, 0); CPCOMMIT();
    issue(1, 1); CPCOMMIT();

    const int l15  = lane & 15;
    const int lseg = (lane >> 4) * 16;

    for (int kt = 0; kt < KC; kt++) {
        const int st = kt % 3;
        CPWAIT1();
        __syncthreads();
        if (kt + 2 < KC) issue(kt + 2, (kt + 2) % 3);
        CPCOMMIT();

        const uint32_t Ab = sb + (uint32_t)st * STAGE_BYTES;
        const uint32_t Bb = Ab + 16384u;

        #pragma unroll
        for (int ks = 0; ks < 2; ks++) {
            const int cbh = ks * 32 + lseg;
            uint32_t a[2][4], bh[4][2], bl[4][2];
            #pragma unroll
            for (int mi = 0; mi < 2; mi++) {
                int row = wm * 32 + mi * 16 + l15;
                LDSM4(a[mi][0], a[mi][1], a[mi][2], a[mi][3],
                      Ab + row * 128 + (cbh ^ ((row & 7) << 4)));
            }
            #pragma unroll
            for (int g = 0; g < 2; g++) {
                int row = wn * 32 + g * 16 + l15;
                uint32_t xr = (row & 7) << 4;
                uint32_t r0, r1, r2, r3;
                LDSM4(r0, r1, r2, r3, Bb + row * 128 + (cbh ^ xr));
                bh[2*g][0] = r0; bh[2*g][1] = r2;
                bh[2*g+1][0] = r1; bh[2*g+1][1] = r3;
                LDSM4(r0, r1, r2, r3, Bb + row * 128 + ((cbh + 64) ^ xr));
                bl[2*g][0] = r0; bl[2*g][1] = r2;
                bl[2*g+1][0] = r1; bl[2*g+1][1] = r3;
            }
            #pragma unroll
            for (int mi = 0; mi < 2; mi++)
                #pragma unroll
                for (int ni = 0; ni < 4; ni++)
                    MMA(c[mi][ni], a[mi][0], a[mi][1], a[mi][2], a[mi][3],
                        bh[ni][0], bh[ni][1]);
            #pragma unroll
            for (int mi = 0; mi < 2; mi++)
                #pragma unroll
                for (int ni = 0; ni < 4; ni++)
                    MMA(c[mi][ni], a[mi][0], a[mi][1], a[mi][2], a[mi][3],
                        bl[ni][0], bl[ni][1]);
            #pragma unroll
            for (int mi = 0; mi < 2; mi++) {
                int row = wm * 32 + mi * 16 + l15;
                LDSM4(a[mi][0], a[mi][1], a[mi][2], a[mi][3],
                      Ab + row * 128 + ((cbh + 64) ^ ((row & 7) << 4)));
            }
            #pragma unroll
            for (int mi = 0; mi < 2; mi++)
                #pragma unroll
                for (int ni = 0; ni < 4; ni++)
                    MMA(c[mi][ni], a[mi][0], a[mi][1], a[mi][2], a[mi][3],
                        bh[ni][0], bh[ni][1]);
        }
    }
}

// ---------------------------------------------------------------------------
// Single-pass fp16 mainloop (att), runtime KC
// ---------------------------------------------------------------------------
__device__ __forceinline__ void gemm_main1(const uint8_t* __restrict__ Ap,
                                           const uint8_t* __restrict__ Bp,
                                           int KC, char* smem, float (&c)[2][4][4])
{
    const int tid  = threadIdx.x;
    const int lane = tid & 31, wid = tid >> 5;
    const int wm = wid >> 1, wn = wid & 1;
    const uint32_t sb = smem_u32(smem);

    #pragma unroll
    for (int mi = 0; mi < 2; mi++)
        #pragma unroll
        for (int ni = 0; ni < 4; ni++)
            #pragma unroll
            for (int q = 0; q < 4; q++) c[mi][ni][q] = 0.f;

    const int ar = tid >> 1;
    const int as = (tid & 1) * 4;
    const uint8_t* asrc = Ap + (size_t)ar * KCS * 128 + as * 16;
    uint32_t dswA[4];
    #pragma unroll
    for (int i = 0; i < 4; i++)
        dswA[i] = (uint32_t)(ar * 128 + (((as + i) * 16) ^ ((ar & 7) << 4)));
    const int br = tid >> 2;
    const int bs = (tid & 3) * 2;
    const uint8_t* bsrc = Bp + (size_t)br * KVS * 128 + bs * 16;
    uint32_t dswB[2];
    #pragma unroll
    for (int i = 0; i < 2; i++)
        dswB[i] = (uint32_t)(br * 128 + (((bs + i) * 16) ^ ((br & 7) << 4)));

    auto issue = [&](int kt, int st) {
        const uint32_t base = sb + (uint32_t)st * STAGE_BYTES;
        const uint8_t* a = asrc + (size_t)kt * 128;
        const uint8_t* b = bsrc + (size_t)kt * 128;
        #pragma unroll
        for (int i = 0; i < 4; i++) CP16(base + dswA[i], a + i * 16);
        #pragma unroll
        for (int i = 0; i < 2; i++) CP16(base + 16384u + dswB[i], b + i * 16);
    };

    issue(0, 0); CPCOMMIT();
    issue(1, 1); CPCOMMIT();

    const int l15  = lane & 15;
    const int lseg = (lane >> 4) * 16;

    for (int kt = 0; kt < KC; kt++) {
        const int st = kt % 3;
        CPWAIT1();
        __syncthreads();
        if (kt + 2 < KC) issue(kt + 2, (kt + 2) % 3);
        CPCOMMIT();

        const uint32_t Ab = sb + (uint32_t)st * STAGE_BYTES;
        const uint32_t Bb = Ab + 16384u;

        #pragma unroll
        for (int ks = 0; ks < 4; ks++) {
            const int cb = ks * 32 + lseg;
            uint32_t a[2][4], bh[4][2];
            #pragma unroll
            for (int mi = 0; mi < 2; mi++) {
                int row = wm * 32 + mi * 16 + l15;
                LDSM4(a[mi][0], a[mi][1], a[mi][2], a[mi][3],
                      Ab + row * 128 + (cb ^ ((row & 7) << 4)));
            }
            #pragma unroll
            for (int g = 0; g < 2; g++) {
                int row = wn * 32 + g * 16 + l15;
                uint32_t xr = (row & 7) << 4;
                uint32_t r0, r1, r2, r3;
                LDSM4(r0, r1, r2, r3, Bb + row * 128 + (cb ^ xr));
                bh[2*g][0] = r0; bh[2*g][1] = r2;
                bh[2*g+1][0] = r1; bh[2*g+1][1] = r3;
            }
            #pragma unroll
            for (int mi = 0; mi < 2; mi++)
                #pragma unroll
                for (int ni = 0; ni < 4; ni++)
                    MMA_H(c[mi][ni], a[mi][0], a[mi][1], a[mi][2], a[mi][3],
                          bh[ni][0], bh[ni][1]);
        }
    }
}

// ---------------------------------------------------------------------------
// Prep kernels
// ---------------------------------------------------------------------------
__global__ __launch_bounds__(256) void index_kernel(const int* __restrict__ mask2)
{
    const int b = blockIdx.x, tid = threadIdx.x;
    __shared__ int wsum[8];
    int4 m = *(const int4*)(mask2 + (size_t)b * LL + tid * 4);
    int keep[4] = { m.x == 0, m.y == 0, m.z == 0, m.w == 0 };
    int cnt4 = keep[0] + keep[1] + keep[2] + keep[3];
    const int lane = tid & 31, wid = tid >> 5;
    int s = cnt4;
    #pragma unroll
    for (int o = 1; o < 32; o <<= 1) {
        int v = __shfl_up_sync(0xffffffffu, s, o);
        if (lane >= o) s += v;
    }
    if (lane == 31) wsum[wid] = s;
    __syncthreads();
    int wb = 0;
    for (int w = 0; w < wid; w++) wb += wsum[w];
    int base = wb + s - cnt4;
    const int j0 = tid * 4;
    #pragma unroll
    for (int q = 0; q < 4; q++)
        if (keep[q]) g_jidx[b][base++] = j0 + q;
    if (tid == 255) g_cnt[b] = wb + s;
}

// x1 only
__global__ __launch_bounds__(256) void pack_x1_kernel(const float* __restrict__ x1)
{
    size_t id = (size_t)blockIdx.x * 256 + threadIdx.x;
    size_t k4 = id * 4;
    int row = (int)(k4 / HH);
    int k   = (int)(k4 - (size_t)row * HH);
    float4 v = *(const float4*)(x1 + k4);
    uint32_t h0, h1, l0, l1;
    split4(v, h0, h1, l0, l1);
    uint32_t* d = (uint32_t*)g_x1p + ((size_t)row * KCP + (k >> 5)) * 32 + ((k & 31) >> 1);
    *(uint2*)d        = make_uint2(h0, h1);
    *(uint2*)(d + 16) = make_uint2(l0, l1);
}

__global__ __launch_bounds__(256) void pack_w_kernel(const float* __restrict__ W)
{
    size_t id = (size_t)blockIdx.x * 256 + threadIdx.x;
    size_t k4 = id * 4;
    int row = (int)(k4 / HH);
    int k   = (int)(k4 - (size_t)row * HH);
    float4 v = *(const float4*)(W + k4);
    uint32_t h0, h1, l0, l1;
    split4(v, h0, h1, l0, l1);
    uint32_t* d = (uint32_t*)g_wp + ((size_t)row * KCP + (k >> 5)) * 32 + ((k & 31) >> 1);
    *(uint2*)d        = make_uint2(h0, h1);
    *(uint2*)(d + 16) = make_uint2(l0, l1);
}

// COMPACT x2 pack: row c of g_x2p = split(x2[jidx[min(c,cnt-1)]]) for c < pad128(cnt)
__global__ __launch_bounds__(192) void pack_x2c_kernel(const float* __restrict__ x2)
{
    const int b = blockIdx.y;
    const int c = blockIdx.x;            // compact row 0..1023
    const int cnt = g_cnt[b];
    if (c >= ((cnt + 127) & ~127)) return;
    const int j = g_jidx[b][c < cnt ? c : cnt - 1];
    const int tid = threadIdx.x;         // 192 threads x 4 floats = 768
    const int k4 = tid * 4;
    float4 v = *(const float4*)(x2 + ((size_t)b * LL + j) * HH + k4);
    uint32_t h0, h1, l0, l1;
    split4(v, h0, h1, l0, l1);
    uint32_t* d = (uint32_t*)g_x2p
                + (((size_t)b * LL + c) * KCP + (k4 >> 5)) * 32 + ((k4 & 31) >> 1);
    *(uint2*)d        = make_uint2(h0, h1);
    *(uint2*)(d + 16) = make_uint2(l0, l1);
}

// Gathered transpose: vtp[h][c] = fp16(x2[jidx[c]][h]) for compact c
__global__ __launch_bounds__(256) void transpose_gather(const float* __restrict__ X2)
{
    __shared__ float t[32][33];
    const int b  = blockIdx.z;
    const int c0 = blockIdx.x * 32;
    const int h0 = blockIdx.y * 32;
    const int cnt = g_cnt[b];
    if (c0 >= ((cnt + 63) & ~63)) return;
    const int tid = threadIdx.x;
    const int tx = tid & 31, ty = tid >> 5;
    #pragma unroll
    for (int i = 0; i < 4; i++) {
        int cc = c0 + ty + i * 8;
        int j = g_jidx[b][cc < cnt ? cc : cnt - 1];
        t[ty + i * 8][tx] = X2[((size_t)b * LL + j) * HH + h0 + tx];
    }
    __syncthreads();
    const int oy = tid >> 3;
    const int ox = (tid & 7) * 4;
    __half2 p01 = __float22half2_rn(make_float2(t[ox][oy],   t[ox+1][oy]));
    __half2 p23 = __float22half2_rn(make_float2(t[ox+2][oy], t[ox+3][oy]));
    const size_t row = (size_t)b * HH + h0 + oy;
    const int chunk = blockIdx.x >> 1;
    uint32_t* d = (uint32_t*)g_vtp + (row * KVS + chunk) * 32
                + (blockIdx.x & 1) * 16 + (ox >> 1);
    *(uint2*)d = make_uint2(*reinterpret_cast<uint32_t*>(&p01),
                            *reinterpret_cast<uint32_t*>(&p23));
}

// ---------------------------------------------------------------------------
// GEMM kernels
// ---------------------------------------------------------------------------
// z=0: x1 flat. z=1: compact x2p rows, early-exit fully-masked tiles.
__global__ __launch_bounds__(256, 3) void proj_gemm(const float* __restrict__ bias)
{
    extern __shared__ char smem[];
    const int z  = blockIdx.z;
    const int y  = blockIdx.y;
    const int m0 = y * 128;
    const int n0 = blockIdx.x * 64;
    const int tid = threadIdx.x;

    if (z == 1) {
        const int b   = y >> 3;
        if (((y & 7) * 128) >= g_cnt[b]) return;   // whole tile masked away
    }
    const uint8_t* a_tsrc = (const uint8_t*)(z ? g_x2p : g_x1p)
        + ((size_t)(m0 + (tid >> 1)) * KCP) * 128 + (tid & 1) * 64;
    const uint8_t* Bp = (const uint8_t*)g_wp + (size_t)n0 * KCP * 128;

    float c[2][4][4];
    gemm_main3(a_tsrc, Bp, KCP, smem, c);

    __syncthreads();
    const int lane = tid & 31, wid = tid >> 5;
    const int wm = wid >> 1, wn = wid & 1;
    #pragma unroll
    for (int mi = 0; mi < 2; mi++) {
        #pragma unroll
        for (int ni = 0; ni < 4; ni++) {
            const int cc = wn * 32 + ni * 8 + 2 * (lane & 3);
            const int gc = n0 + cc;
            const float b0 = bias[gc], b1 = bias[gc + 1];
            #pragma unroll
            for (int hrow = 0; hrow < 2; hrow++) {
                const int r = wm * 32 + mi * 16 + (lane >> 2) + 8 * hrow;
                float v0 = fmaxf(c[mi][ni][2*hrow + 0] + b0, 0.f);
                float v1 = fmaxf(c[mi][ni][2*hrow + 1] + b1, 0.f);
                __nv_bfloat162 h = __floats2bfloat162_rn(v0, v1);
                float2 f = __bfloat1622float2(h);
                __nv_bfloat162 l = __floats2bfloat162_rn(v0 - f.x, v1 - f.y);
                uint32_t off = (uint32_t)(r * 256 + (cc >> 5) * 128 + (cc & 31) * 2);
                *(uint32_t*)(smem + off)      = *reinterpret_cast<uint32_t*>(&h);
                *(uint32_t*)(smem + off + 64) = *reinterpret_cast<uint32_t*>(&l);
            }
        }
    }
    __syncthreads();
    uint4* dst = (z ? g_ypp : g_xpp);
    const uint4* ssrc = (const uint4*)smem;
    #pragma unroll
    for (int i = 0; i < 8; i++) {
        int idx = i * 256 + tid;
        int r   = idx >> 4;
        int ci  = (idx >> 3) & 1;
        int seg = idx & 7;
        dst[((size_t)(m0 + r) * KCP + (n0 >> 5) + ci) * 8 + seg] = ssrc[idx];
    }
}

// scores over compacted n-columns only
__global__ __launch_bounds__(256, 3) void scores_gemm()
{
    extern __shared__ char smem[];
    const int b  = blockIdx.z;
    const int m0 = blockIdx.y * 128;
    const int n0 = blockIdx.x * 64;
    if (n0 >= g_cnt[b]) return;
    const int tid = threadIdx.x;
    const uint8_t* a_tsrc = (const uint8_t*)g_xpp
        + ((size_t)(b * LL + m0 + (tid >> 1)) * KCP) * 128 + (tid & 1) * 64;
    const uint8_t* Bp = (const uint8_t*)g_ypp + (size_t)(b * LL + n0) * KCP * 128;

    float c[2][4][4];
    gemm_main3(a_tsrc, Bp, KCP, smem, c);

    const int lane = tid & 31, wid = tid >> 5;
    const int wm = wid >> 1, wn = wid & 1;
    float* C = g_sc + ((size_t)b * LL + m0) * LL + n0;
    #pragma unroll
    for (int mi = 0; mi < 2; mi++) {
        const int r0 = wm * 32 + mi * 16 + (lane >> 2);
        #pragma unroll
        for (int ni = 0; ni < 4; ni++) {
            const int cc = wn * 32 + ni * 8 + 2 * (lane & 3);
            *(float2*)(C + (size_t)r0 * LL + cc)       = make_float2(c[mi][ni][0], c[mi][ni][1]);
            *(float2*)(C + (size_t)(r0 + 8) * LL + cc) = make_float2(c[mi][ni][2], c[mi][ni][3]);
        }
    }
}

// softmax over compacted columns; loads and alpha-writes restricted to live region
__global__ __launch_bounds__(256) void softmax_pack()
{
    const int b = blockIdx.y, i = blockIdx.x, tid = threadIdx.x;
    const float* row = g_sc + ((size_t)b * LL + i) * LL;
    const int cnt = g_cnt[b];
    const int KCb = (cnt + 63) >> 6;

    const int j0 = tid * 4;
    float4 s = make_float4(0.f, 0.f, 0.f, 0.f);
    if (j0 < cnt) s = *(const float4*)(row + j0);
    float v[4];
    v[0] = (j0 + 0 < cnt) ? s.x : -INFINITY;
    v[1] = (j0 + 1 < cnt) ? s.y : -INFINITY;
    v[2] = (j0 + 2 < cnt) ? s.z : -INFINITY;
    v[3] = (j0 + 3 < cnt) ? s.w : -INFINITY;

    float mx = fmaxf(fmaxf(v[0], v[1]), fmaxf(v[2], v[3]));
    #pragma unroll
    for (int o = 16; o > 0; o >>= 1) mx = fmaxf(mx, __shfl_xor_sync(0xffffffffu, mx, o));

    __shared__ float red[8];
    if ((tid & 31) == 0) red[tid >> 5] = mx;
    __syncthreads();
    float bm = red[0];
    #pragma unroll
    for (int w = 1; w < 8; w++) bm = fmaxf(bm, red[w]);

    float e[4];
    float sum = 0.f;
    #pragma unroll
    for (int q = 0; q < 4; q++) { e[q] = expf(v[q] - bm); sum += e[q]; }
    #pragma unroll
    for (int o = 16; o > 0; o >>= 1) sum += __shfl_xor_sync(0xffffffffu, sum, o);

    __syncthreads();
    if ((tid & 31) == 0) red[tid >> 5] = sum;
    __syncthreads();
    float bs = 0.f;
    #pragma unroll
    for (int w = 0; w < 8; w++) bs += red[w];
    const float inv = 1.0f / bs;

    const int chunk = tid >> 4;
    if (chunk < KCb) {   // att reads only KCb chunks; skip dead writes
        __half2 p01 = __float22half2_rn(make_float2(e[0]*inv, e[1]*inv));
        __half2 p23 = __float22half2_rn(make_float2(e[2]*inv, e[3]*inv));
        uint32_t* d = (uint32_t*)g_ap + (((size_t)b * LL + i) * KCS + chunk) * 32
                    + (tid & 15) * 2;
        *(uint2*)d = make_uint2(*reinterpret_cast<uint32_t*>(&p01),
                                *reinterpret_cast<uint32_t*>(&p23));
    }
}

// att with per-batch runtime K = ceil(cnt/64) chunks
__global__ __launch_bounds__(256, 3) void att_gemm(const float* __restrict__ X1,
                                                   float* __restrict__ OUT)
{
    extern __shared__ char smem[];
    const int b  = blockIdx.z;
    const int m0 = blockIdx.y * 128;
    const int n0 = blockIdx.x * 64;
    const int KCb = (g_cnt[b] + 63) >> 6;
    const uint8_t* Ap = (const uint8_t*)g_ap  + (size_t)(b * LL + m0) * KCS * 128;
    const uint8_t* Bp = (const uint8_t*)g_vtp + (size_t)(b * HH + n0) * KVS * 128;

    float c[2][4][4];
    gemm_main1(Ap, Bp, KCb, smem, c);

    const int lane = threadIdx.x & 31, wid = threadIdx.x >> 5;
    const int wm = wid >> 1, wn = wid & 1;
    #pragma unroll
    for (int mi = 0; mi < 2; mi++) {
        const int r0 = m0 + wm * 32 + mi * 16 + (lane >> 2);
        #pragma unroll
        for (int ni = 0; ni < 4; ni++) {
            const int cc = wn * 32 + ni * 8 + 2 * (lane & 3);
            #pragma unroll
            for (int hrow = 0; hrow < 2; hrow++) {
                const int gr = r0 + 8 * hrow;
                float2 a = make_float2(c[mi][ni][2*hrow + 0], c[mi][ni][2*hrow + 1]);
                const float* xp = X1  + ((size_t)b * LL + gr) * HH   + n0 + cc;
                float*       op = OUT + ((size_t)b * LL + gr) * OUTW + n0 + cc;
                float2 x = *(const float2*)xp;
                *(float2*)(op)          = x;
                *(float2*)(op + HH)     = a;
                *(float2*)(op + 2*HH)   = make_float2(x.x * a.x, x.y * a.y);
                *(float2*)(op + 3*HH)   = make_float2(x.x - a.x, x.y - a.y);
            }
        }
    }
}

// ---------------------------------------------------------------------------
extern "C" void kernel_launch(void* const* d_in, const int* in_sizes, int n_in,
                              void* d_out, int out_size)
{
    (void)in_sizes; (void)n_in; (void)out_size;
    const float* x1   = (const float*)d_in[0];
    const float* x2   = (const float*)d_in[1];
    const int*   x2m  = (const int*)d_in[3];
    const float* W    = (const float*)d_in[4];
    const float* bias = (const float*)d_in[5];
    float*       out  = (float*)d_out;

    cudaFuncSetAttribute(proj_gemm,   cudaFuncAttributeMaxDynamicSharedMemorySize, SMEM_BYTES);
    cudaFuncSetAttribute(scores_gemm, cudaFuncAttributeMaxDynamicSharedMemorySize, SMEM_BYTES);
    cudaFuncSetAttribute(att_gemm,    cudaFuncAttributeMaxDynamicSharedMemorySize, SMEM_BYTES);

    index_kernel<<<NB, 256>>>(x2m);

    pack_x1_kernel<<<(NB*LL*HH/4)/256, 256>>>(x1);
    pack_w_kernel<<<(HH*HH/4)/256, 256>>>(W);

    dim3 gXC(LL, NB);
    pack_x2c_kernel<<<gXC, 192>>>(x2);

    dim3 gT(LL/32, HH/32, NB);
    transpose_gather<<<gT, 256>>>(x2);

    dim3 gP(HH/64, (NB*LL)/128, 2);         // (12, 128, 2)
    proj_gemm<<<gP, 256, SMEM_BYTES>>>(bias);

    dim3 gS(LL/64, LL/128, NB);             // (16, 8, 16)
    scores_gemm<<<gS, 256, SMEM_BYTES>>>();

    dim3 gM(LL, NB);
    softmax_pack<<<gM, 256>>>();

    dim3 gA(HH/64, LL/128, NB);             // (12, 8, 16)
    att_gemm<<<gA, 256, SMEM_BYTES>>>(x1, out);
}

// round 15
// speedup vs baseline: 1.5237x; 1.5237x over previous
#include <cuda_runtime.h>
#include <cuda_bf16.h>
#include <cuda_fp16.h>
#include <math.h>
#include <stdint.h>

#define NB 16
#define LL 1024
#define HH 768
#define OUTW (4*HH)
#define KCP (HH/32)   // 24 hi/lo k32-chunks for proj/scores operands
#define KCS (LL/64)   // 16 fp16 k64-chunks (max) for att operands
#define KVS (LL/64)

// ---------------------------------------------------------------------------
// Packed scratch
// ---------------------------------------------------------------------------
__device__ uint4 g_x1p[(size_t)NB*LL*KCP*8];   // 48 MB hi/lo
__device__ uint4 g_x2p[(size_t)NB*LL*KCP*8];   // 48 MB hi/lo (COMPACT rows)
__device__ uint4 g_wp [(size_t)HH*KCP*8];      // 2.25 MB hi/lo
__device__ uint4 g_xpp[(size_t)NB*LL*KCP*8];   // 48 MB hi/lo
__device__ uint4 g_ypp[(size_t)NB*LL*KCP*8];   // 48 MB hi/lo (COMPACT rows)
__device__ uint4 g_ap [(size_t)NB*LL*KCS*8];   // 32 MB fp16 alpha (compact j')
__device__ uint4 g_vtp[(size_t)NB*HH*KVS*8];   // 24 MB fp16 x2^T (compact j')
__device__ float g_sc [(size_t)NB*LL*LL];      // 64 MB scores fp32 (compact cols)
__device__ int   g_jidx[NB][LL];               // compacted j index per batch
__device__ int   g_cnt [NB];                   // unmasked count per batch

// ---------------------------------------------------------------------------
__device__ __forceinline__ uint32_t smem_u32(const void* p) {
    uint32_t a;
    asm("{ .reg .u64 t; cvta.to.shared.u64 t, %1; cvt.u32.u64 %0, t; }"
        : "=r"(a) : "l"(p));
    return a;
}

__device__ __forceinline__ void split4(float4 v, uint32_t& h0, uint32_t& h1,
                                       uint32_t& l0, uint32_t& l1) {
    __nv_bfloat162 a = __floats2bfloat162_rn(v.x, v.y);
    __nv_bfloat162 b = __floats2bfloat162_rn(v.z, v.w);
    float2 fa = __bfloat1622float2(a), fb = __bfloat1622float2(b);
    __nv_bfloat162 c = __floats2bfloat162_rn(v.x - fa.x, v.y - fa.y);
    __nv_bfloat162 d = __floats2bfloat162_rn(v.z - fb.x, v.w - fb.y);
    h0 = *reinterpret_cast<uint32_t*>(&a);
    h1 = *reinterpret_cast<uint32_t*>(&b);
    l0 = *reinterpret_cast<uint32_t*>(&c);
    l1 = *reinterpret_cast<uint32_t*>(&d);
}

#define CP16(dst, src) \
    asm volatile("cp.async.cg.shared.global [%0], [%1], 16;" :: "r"(dst), "l"(src))
#define CPCOMMIT() asm volatile("cp.async.commit_group;" ::: "memory")
#define CPWAIT1()  asm volatile("cp.async.wait_group 1;" ::: "memory")

#define LDSM4(r0,r1,r2,r3,addr) \
    asm volatile("ldmatrix.sync.aligned.m8n8.x4.shared.b16 {%0,%1,%2,%3}, [%4];" \
                 : "=r"(r0),"=r"(r1),"=r"(r2),"=r"(r3) : "r"(addr))

#define MMA(c,a0,a1,a2,a3,b0,b1) \
    asm volatile("mma.sync.aligned.m16n8k16.row.col.f32.bf16.bf16.f32 " \
                 "{%0,%1,%2,%3}, {%4,%5,%6,%7}, {%8,%9}, {%0,%1,%2,%3};" \
                 : "+f"((c)[0]),"+f"((c)[1]),"+f"((c)[2]),"+f"((c)[3]) \
                 : "r"(a0),"r"(a1),"r"(a2),"r"(a3),"r"(b0),"r"(b1))

#define MMA_H(c,a0,a1,a2,a3,b0,b1) \
    asm volatile("mma.sync.aligned.m16n8k16.row.col.f32.f16.f16.f32 " \
                 "{%0,%1,%2,%3}, {%4,%5,%6,%7}, {%8,%9}, {%0,%1,%2,%3};" \
                 : "+f"((c)[0]),"+f"((c)[1]),"+f"((c)[2]),"+f"((c)[3]) \
                 : "r"(a0),"r"(a1),"r"(a2),"r"(a3),"r"(b0),"r"(b1))

// CTA tile 128x64: stage = A 16KB + B 8KB
#define STAGE_BYTES 24576u
#define SMEM_BYTES  (3 * 24576)

// ---------------------------------------------------------------------------
// 3-pass split-bf16 mainloop. a_tsrc = THIS thread's A source (row + seg resolved).
// ---------------------------------------------------------------------------
__device__ __forceinline__ void gemm_main3(const uint8_t* __restrict__ a_tsrc,
                                           const uint8_t* __restrict__ Bp,
                                           int KC, char* smem, float (&c)[2][4][4])
{
    const int tid  = threadIdx.x;
    const int lane = tid & 31, wid = tid >> 5;
    const int wm = wid >> 1, wn = wid & 1;
    const uint32_t sb = smem_u32(smem);

    #pragma unroll
    for (int mi = 0; mi < 2; mi++)
        #pragma unroll
        for (int ni = 0; ni < 4; ni++)
            #pragma unroll
            for (int q = 0; q < 4; q++) c[mi][ni][q] = 0.f;

    const int ar = tid >> 1;
    const int as = (tid & 1) * 4;
    uint32_t dswA[4];
    #pragma unroll
    for (int i = 0; i < 4; i++)
        dswA[i] = (uint32_t)(ar * 128 + (((as + i) * 16) ^ ((ar & 7) << 4)));
    const int br = tid >> 2;
    const int bs = (tid & 3) * 2;
    const uint8_t* bsrc = Bp + (size_t)br * KC * 128 + bs * 16;
    uint32_t dswB[2];
    #pragma unroll
    for (int i = 0; i < 2; i++)
        dswB[i] = (uint32_t)(br * 128 + (((bs + i) * 16) ^ ((br & 7) << 4)));

    auto issue = [&](int kt, int st) {
        const uint32_t base = sb + (uint32_t)st * STAGE_BYTES;
        const uint8_t* a = a_tsrc + (size_t)kt * 128;
        const uint8_t* b = bsrc + (size_t)kt * 128;
        #pragma unroll
        for (int i = 0; i < 4; i++) CP16(base + dswA[i], a + i * 16);
        #pragma unroll
        for (int i = 0; i < 2; i++) CP16(base + 16384u + dswB[i], b + i * 16);
    };

    issue(0, 0); CPCOMMIT();
    issue(1, 1); CPCOMMIT();

    const int l15  = lane & 15;
    const int lseg = (lane >> 4) * 16;

    for (int kt = 0; kt < KC; kt++) {
        const int st = kt % 3;
        CPWAIT1();
        __syncthreads();
        if (kt + 2 < KC) issue(kt + 2, (kt + 2) % 3);
        CPCOMMIT();

        const uint32_t Ab = sb + (uint32_t)st * STAGE_BYTES;
        const uint32_t Bb = Ab + 16384u;

        #pragma unroll
        for (int ks = 0; ks < 2; ks++) {
            const int cbh = ks * 32 + lseg;
            uint32_t a[2][4], bh[4][2], bl[4][2];
            #pragma unroll
            for (int mi = 0; mi < 2; mi++) {
                int row = wm * 32 + mi * 16 + l15;
                LDSM4(a[mi][0], a[mi][1], a[mi][2], a[mi][3],
                      Ab + row * 128 + (cbh ^ ((row & 7) << 4)));
            }
            #pragma unroll
            for (int g = 0; g < 2; g++) {
                int row = wn * 32 + g * 16 + l15;
                uint32_t xr = (row & 7) << 4;
                uint32_t r0, r1, r2, r3;
                LDSM4(r0, r1, r2, r3, Bb + row * 128 + (cbh ^ xr));
                bh[2*g][0] = r0; bh[2*g][1] = r2;
                bh[2*g+1][0] = r1; bh[2*g+1][1] = r3;
                LDSM4(r0, r1, r2, r3, Bb + row * 128 + ((cbh + 64) ^ xr));
                bl[2*g][0] = r0; bl[2*g][1] = r2;
                bl[2*g+1][0] = r1; bl[2*g+1][1] = r3;
            }
            #pragma unroll
            for (int mi = 0; mi < 2; mi++)
                #pragma unroll
                for (int ni = 0; ni < 4; ni++)
                    MMA(c[mi][ni], a[mi][0], a[mi][1], a[mi][2], a[mi][3],
                        bh[ni][0], bh[ni][1]);
            #pragma unroll
            for (int mi = 0; mi < 2; mi++)
                #pragma unroll
                for (int ni = 0; ni < 4; ni++)
                    MMA(c[mi][ni], a[mi][0], a[mi][1], a[mi][2], a[mi][3],
                        bl[ni][0], bl[ni][1]);
            #pragma unroll
            for (int mi = 0; mi < 2; mi++) {
                int row = wm * 32 + mi * 16 + l15;
                LDSM4(a[mi][0], a[mi][1], a[mi][2], a[mi][3],
                      Ab + row * 128 + ((cbh + 64) ^ ((row & 7) << 4)));
            }
            #pragma unroll
            for (int mi = 0; mi < 2; mi++)
                #pragma unroll
                for (int ni = 0; ni < 4; ni++)
                    MMA(c[mi][ni], a[mi][0], a[mi][1], a[mi][2], a[mi][3],
                        bh[ni][0], bh[ni][1]);
        }
    }
}

// ---------------------------------------------------------------------------
// Single-pass fp16 mainloop (att), runtime KC
// ---------------------------------------------------------------------------
__device__ __forceinline__ void gemm_main1(const uint8_t* __restrict__ Ap,
                                           const uint8_t* __restrict__ Bp,
                                           int KC, char* smem, float (&c)[2][4][4])
{
    const int tid  = threadIdx.x;
    const int lane = tid & 31, wid = tid >> 5;
    const int wm = wid >> 1, wn = wid & 1;
    const uint32_t sb = smem_u32(smem);

    #pragma unroll
    for (int mi = 0; mi < 2; mi++)
        #pragma unroll
        for (int ni = 0; ni < 4; ni++)
            #pragma unroll
            for (int q = 0; q < 4; q++) c[mi][ni][q] = 0.f;

    const int ar = tid >> 1;
    const int as = (tid & 1) * 4;
    const uint8_t* asrc = Ap + (size_t)ar * KCS * 128 + as * 16;
    uint32_t dswA[4];
    #pragma unroll
    for (int i = 0; i < 4; i++)
        dswA[i] = (uint32_t)(ar * 128 + (((as + i) * 16) ^ ((ar & 7) << 4)));
    const int br = tid >> 2;
    const int bs = (tid & 3) * 2;
    const uint8_t* bsrc = Bp + (size_t)br * KVS * 128 + bs * 16;
    uint32_t dswB[2];
    #pragma unroll
    for (int i = 0; i < 2; i++)
        dswB[i] = (uint32_t)(br * 128 + (((bs + i) * 16) ^ ((br & 7) << 4)));

    auto issue = [&](int kt, int st) {
        const uint32_t base = sb + (uint32_t)st * STAGE_BYTES;
        const uint8_t* a = asrc + (size_t)kt * 128;
        const uint8_t* b = bsrc + (size_t)kt * 128;
        #pragma unroll
        for (int i = 0; i < 4; i++) CP16(base + dswA[i], a + i * 16);
        #pragma unroll
        for (int i = 0; i < 2; i++) CP16(base + 16384u + dswB[i], b + i * 16);
    };

    issue(0, 0); CPCOMMIT();
    issue(1, 1); CPCOMMIT();

    const int l15  = lane & 15;
    const int lseg = (lane >> 4) * 16;

    for (int kt = 0; kt < KC; kt++) {
        const int st = kt % 3;
        CPWAIT1();
        __syncthreads();
        if (kt + 2 < KC) issue(kt + 2, (kt + 2) % 3);
        CPCOMMIT();

        const uint32_t Ab = sb + (uint32_t)st * STAGE_BYTES;
        const uint32_t Bb = Ab + 16384u;

        #pragma unroll
        for (int ks = 0; ks < 4; ks++) {
            const int cb = ks * 32 + lseg;
            uint32_t a[2][4], bh[4][2];
            #pragma unroll
            for (int mi = 0; mi < 2; mi++) {
                int row = wm * 32 + mi * 16 + l15;
                LDSM4(a[mi][0], a[mi][1], a[mi][2], a[mi][3],
                      Ab + row * 128 + (cb ^ ((row & 7) << 4)));
            }
            #pragma unroll
            for (int g = 0; g < 2; g++) {
                int row = wn * 32 + g * 16 + l15;
                uint32_t xr = (row & 7) << 4;
                uint32_t r0, r1, r2, r3;
                LDSM4(r0, r1, r2, r3, Bb + row * 128 + (cb ^ xr));
                bh[2*g][0] = r0; bh[2*g][1] = r2;
                bh[2*g+1][0] = r1; bh[2*g+1][1] = r3;
            }
            #pragma unroll
            for (int mi = 0; mi < 2; mi++)
                #pragma unroll
                for (int ni = 0; ni < 4; ni++)
                    MMA_H(c[mi][ni], a[mi][0], a[mi][1], a[mi][2], a[mi][3],
                          bh[ni][0], bh[ni][1]);
        }
    }
}

// ---------------------------------------------------------------------------
// Prep kernels
// ---------------------------------------------------------------------------
__global__ __launch_bounds__(256) void index_kernel(const int* __restrict__ mask2)
{
    const int b = blockIdx.x, tid = threadIdx.x;
    __shared__ int wsum[8];
    int4 m = *(const int4*)(mask2 + (size_t)b * LL + tid * 4);
    int keep[4] = { m.x == 0, m.y == 0, m.z == 0, m.w == 0 };
    int cnt4 = keep[0] + keep[1] + keep[2] + keep[3];
    const int lane = tid & 31, wid = tid >> 5;
    int s = cnt4;
    #pragma unroll
    for (int o = 1; o < 32; o <<= 1) {
        int v = __shfl_up_sync(0xffffffffu, s, o);
        if (lane >= o) s += v;
    }
    if (lane == 31) wsum[wid] = s;
    __syncthreads();
    int wb = 0;
    for (int w = 0; w < wid; w++) wb += wsum[w];
    int base = wb + s - cnt4;
    const int j0 = tid * 4;
    #pragma unroll
    for (int q = 0; q < 4; q++)
        if (keep[q]) g_jidx[b][base++] = j0 + q;
    if (tid == 255) g_cnt[b] = wb + s;
}

// x1 only
__global__ __launch_bounds__(256) void pack_x1_kernel(const float* __restrict__ x1)
{
    size_t id = (size_t)blockIdx.x * 256 + threadIdx.x;
    size_t k4 = id * 4;
    int row = (int)(k4 / HH);
    int k   = (int)(k4 - (size_t)row * HH);
    float4 v = *(const float4*)(x1 + k4);
    uint32_t h0, h1, l0, l1;
    split4(v, h0, h1, l0, l1);
    uint32_t* d = (uint32_t*)g_x1p + ((size_t)row * KCP + (k >> 5)) * 32 + ((k & 31) >> 1);
    *(uint2*)d        = make_uint2(h0, h1);
    *(uint2*)(d + 16) = make_uint2(l0, l1);
}

__global__ __launch_bounds__(256) void pack_w_kernel(const float* __restrict__ W)
{
    size_t id = (size_t)blockIdx.x * 256 + threadIdx.x;
    size_t k4 = id * 4;
    int row = (int)(k4 / HH);
    int k   = (int)(k4 - (size_t)row * HH);
    float4 v = *(const float4*)(W + k4);
    uint32_t h0, h1, l0, l1;
    split4(v, h0, h1, l0, l1);
    uint32_t* d = (uint32_t*)g_wp + ((size_t)row * KCP + (k >> 5)) * 32 + ((k & 31) >> 1);
    *(uint2*)d        = make_uint2(h0, h1);
    *(uint2*)(d + 16) = make_uint2(l0, l1);
}

// COMPACT x2 pack: row c of g_x2p = split(x2[jidx[min(c,cnt-1)]]) for c < pad128(cnt)
__global__ __launch_bounds__(192) void pack_x2c_kernel(const float* __restrict__ x2)
{
    const int b = blockIdx.y;
    const int c = blockIdx.x;            // compact row 0..1023
    const int cnt = g_cnt[b];
    if (c >= ((cnt + 127) & ~127)) return;
    const int j = g_jidx[b][c < cnt ? c : cnt - 1];
    const int tid = threadIdx.x;         // 192 threads x 4 floats = 768
    const int k4 = tid * 4;
    float4 v = *(const float4*)(x2 + ((size_t)b * LL + j) * HH + k4);
    uint32_t h0, h1, l0, l1;
    split4(v, h0, h1, l0, l1);
    uint32_t* d = (uint32_t*)g_x2p
                + (((size_t)b * LL + c) * KCP + (k4 >> 5)) * 32 + ((k4 & 31) >> 1);
    *(uint2*)d        = make_uint2(h0, h1);
    *(uint2*)(d + 16) = make_uint2(l0, l1);
}

// Gathered transpose: vtp[h][c] = fp16(x2[jidx[c]][h]) for compact c
__global__ __launch_bounds__(256) void transpose_gather(const float* __restrict__ X2)
{
    __shared__ float t[32][33];
    const int b  = blockIdx.z;
    const int c0 = blockIdx.x * 32;
    const int h0 = blockIdx.y * 32;
    const int cnt = g_cnt[b];
    if (c0 >= ((cnt + 63) & ~63)) return;
    const int tid = threadIdx.x;
    const int tx = tid & 31, ty = tid >> 5;
    #pragma unroll
    for (int i = 0; i < 4; i++) {
        int cc = c0 + ty + i * 8;
        int j = g_jidx[b][cc < cnt ? cc : cnt - 1];
        t[ty + i * 8][tx] = X2[((size_t)b * LL + j) * HH + h0 + tx];
    }
    __syncthreads();
    const int oy = tid >> 3;
    const int ox = (tid & 7) * 4;
    __half2 p01 = __float22half2_rn(make_float2(t[ox][oy],   t[ox+1][oy]));
    __half2 p23 = __float22half2_rn(make_float2(t[ox+2][oy], t[ox+3][oy]));
    const size_t row = (size_t)b * HH + h0 + oy;
    const int chunk = blockIdx.x >> 1;
    uint32_t* d = (uint32_t*)g_vtp + (row * KVS + chunk) * 32
                + (blockIdx.x & 1) * 16 + (ox >> 1);
    *(uint2*)d = make_uint2(*reinterpret_cast<uint32_t*>(&p01),
                            *reinterpret_cast<uint32_t*>(&p23));
}

// ---------------------------------------------------------------------------
// GEMM kernels
// ---------------------------------------------------------------------------
// z=0: x1 flat. z=1: compact x2p rows, early-exit fully-masked tiles.
__global__ __launch_bounds__(256, 3) void proj_gemm(const float* __restrict__ bias)
{
    extern __shared__ char smem[];
    const int z  = blockIdx.z;
    const int y  = blockIdx.y;
    const int m0 = y * 128;
    const int n0 = blockIdx.x * 64;
    const int tid = threadIdx.x;

    if (z == 1) {
        const int b   = y >> 3;
        if (((y & 7) * 128) >= g_cnt[b]) return;   // whole tile masked away
    }
    const uint8_t* a_tsrc = (const uint8_t*)(z ? g_x2p : g_x1p)
        + ((size_t)(m0 + (tid >> 1)) * KCP) * 128 + (tid & 1) * 64;
    const uint8_t* Bp = (const uint8_t*)g_wp + (size_t)n0 * KCP * 128;

    float c[2][4][4];
    gemm_main3(a_tsrc, Bp, KCP, smem, c);

    __syncthreads();
    const int lane = tid & 31, wid = tid >> 5;
    const int wm = wid >> 1, wn = wid & 1;
    #pragma unroll
    for (int mi = 0; mi < 2; mi++) {
        #pragma unroll
        for (int ni = 0; ni < 4; ni++) {
            const int cc = wn * 32 + ni * 8 + 2 * (lane & 3);
            const int gc = n0 + cc;
            const float b0 = bias[gc], b1 = bias[gc + 1];
            #pragma unroll
            for (int hrow = 0; hrow < 2; hrow++) {
                const int r = wm * 32 + mi * 16 + (lane >> 2) + 8 * hrow;
                float v0 = fmaxf(c[mi][ni][2*hrow + 0] + b0, 0.f);
                float v1 = fmaxf(c[mi][ni][2*hrow + 1] + b1, 0.f);
                __nv_bfloat162 h = __floats2bfloat162_rn(v0, v1);
                float2 f = __bfloat1622float2(h);
                __nv_bfloat162 l = __floats2bfloat162_rn(v0 - f.x, v1 - f.y);
                uint32_t off = (uint32_t)(r * 256 + (cc >> 5) * 128 + (cc & 31) * 2);
                *(uint32_t*)(smem + off)      = *reinterpret_cast<uint32_t*>(&h);
                *(uint32_t*)(smem + off + 64) = *reinterpret_cast<uint32_t*>(&l);
            }
        }
    }
    __syncthreads();
    uint4* dst = (z ? g_ypp : g_xpp);
    const uint4* ssrc = (const uint4*)smem;
    #pragma unroll
    for (int i = 0; i < 8; i++) {
        int idx = i * 256 + tid;
        int r   = idx >> 4;
        int ci  = (idx >> 3) & 1;
        int seg = idx & 7;
        dst[((size_t)(m0 + r) * KCP + (n0 >> 5) + ci) * 8 + seg] = ssrc[idx];
    }
}

// scores over compacted n-columns only
__global__ __launch_bounds__(256, 3) void scores_gemm()
{
    extern __shared__ char smem[];
    const int b  = blockIdx.z;
    const int m0 = blockIdx.y * 128;
    const int n0 = blockIdx.x * 64;
    if (n0 >= g_cnt[b]) return;
    const int tid = threadIdx.x;
    const uint8_t* a_tsrc = (const uint8_t*)g_xpp
        + ((size_t)(b * LL + m0 + (tid >> 1)) * KCP) * 128 + (tid & 1) * 64;
    const uint8_t* Bp = (const uint8_t*)g_ypp + (size_t)(b * LL + n0) * KCP * 128;

    float c[2][4][4];
    gemm_main3(a_tsrc, Bp, KCP, smem, c);

    const int lane = tid & 31, wid = tid >> 5;
    const int wm = wid >> 1, wn = wid & 1;
    float* C = g_sc + ((size_t)b * LL + m0) * LL + n0;
    #pragma unroll
    for (int mi = 0; mi < 2; mi++) {
        const int r0 = wm * 32 + mi * 16 + (lane >> 2);
        #pragma unroll
        for (int ni = 0; ni < 4; ni++) {
            const int cc = wn * 32 + ni * 8 + 2 * (lane & 3);
            *(float2*)(C + (size_t)r0 * LL + cc)       = make_float2(c[mi][ni][0], c[mi][ni][1]);
            *(float2*)(C + (size_t)(r0 + 8) * LL + cc) = make_float2(c[mi][ni][2], c[mi][ni][3]);
        }
    }
}

// softmax over compacted columns; loads and alpha-writes restricted to live region
__global__ __launch_bounds__(256) void softmax_pack()
{
    const int b = blockIdx.y, i = blockIdx.x, tid = threadIdx.x;
    const float* row = g_sc + ((size_t)b * LL + i) * LL;
    const int cnt = g_cnt[b];
    const int KCb = (cnt + 63) >> 6;

    const int j0 = tid * 4;
    float4 s = make_float4(0.f, 0.f, 0.f, 0.f);
    if (j0 < cnt) s = *(const float4*)(row + j0);
    float v[4];
    v[0] = (j0 + 0 < cnt) ? s.x : -INFINITY;
    v[1] = (j0 + 1 < cnt) ? s.y : -INFINITY;
    v[2] = (j0 + 2 < cnt) ? s.z : -INFINITY;
    v[3] = (j0 + 3 < cnt) ? s.w : -INFINITY;

    float mx = fmaxf(fmaxf(v[0], v[1]), fmaxf(v[2], v[3]));
    #pragma unroll
    for (int o = 16; o > 0; o >>= 1) mx = fmaxf(mx, __shfl_xor_sync(0xffffffffu, mx, o));

    __shared__ float red[8];
    if ((tid & 31) == 0) red[tid >> 5] = mx;
    __syncthreads();
    float bm = red[0];
    #pragma unroll
    for (int w = 1; w < 8; w++) bm = fmaxf(bm, red[w]);

    float e[4];
    float sum = 0.f;
    #pragma unroll
    for (int q = 0; q < 4; q++) { e[q] = expf(v[q] - bm); sum += e[q]; }
    #pragma unroll
    for (int o = 16; o > 0; o >>= 1) sum += __shfl_xor_sync(0xffffffffu, sum, o);

    __syncthreads();
    if ((tid & 31) == 0) red[tid >> 5] = sum;
    __syncthreads();
    float bs = 0.f;
    #pragma unroll
    for (int w = 0; w < 8; w++) bs += red[w];
    const float inv = 1.0f / bs;

    const int chunk = tid >> 4;
    if (chunk < KCb) {   // att reads only KCb chunks; skip dead writes
        __half2 p01 = __float22half2_rn(make_float2(e[0]*inv, e[1]*inv));
        __half2 p23 = __float22half2_rn(make_float2(e[2]*inv, e[3]*inv));
        uint32_t* d = (uint32_t*)g_ap + (((size_t)b * LL + i) * KCS + chunk) * 32
                    + (tid & 15) * 2;
        *(uint2*)d = make_uint2(*reinterpret_cast<uint32_t*>(&p01),
                                *reinterpret_cast<uint32_t*>(&p23));
    }
}

// att with per-batch runtime K = ceil(cnt/64) chunks
__global__ __launch_bounds__(256, 3) void att_gemm(const float* __restrict__ X1,
                                                   float* __restrict__ OUT)
{
    extern __shared__ char smem[];
    const int b  = blockIdx.z;
    const int m0 = blockIdx.y * 128;
    const int n0 = blockIdx.x * 64;
    const int KCb = (g_cnt[b] + 63) >> 6;
    const uint8_t* Ap = (const uint8_t*)g_ap  + (size_t)(b * LL + m0) * KCS * 128;
    const uint8_t* Bp = (const uint8_t*)g_vtp + (size_t)(b * HH + n0) * KVS * 128;

    float c[2][4][4];
    gemm_main1(Ap, Bp, KCb, smem, c);

    const int lane = threadIdx.x & 31, wid = threadIdx.x >> 5;
    const int wm = wid >> 1, wn = wid & 1;
    #pragma unroll
    for (int mi = 0; mi < 2; mi++) {
        const int r0 = m0 + wm * 32 + mi * 16 + (lane >> 2);
        #pragma unroll
        for (int ni = 0; ni < 4; ni++) {
            const int cc = wn * 32 + ni * 8 + 2 * (lane & 3);
            #pragma unroll
            for (int hrow = 0; hrow < 2; hrow++) {
                const int gr = r0 + 8 * hrow;
                float2 a = make_float2(c[mi][ni][2*hrow + 0], c[mi][ni][2*hrow + 1]);
                const float* xp = X1  + ((size_t)b * LL + gr) * HH   + n0 + cc;
                float*       op = OUT + ((size_t)b * LL + gr) * OUTW + n0 + cc;
                float2 x = *(const float2*)xp;
                *(float2*)(op)          = x;
                *(float2*)(op + HH)     = a;
                *(float2*)(op + 2*HH)   = make_float2(x.x * a.x, x.y * a.y);
                *(float2*)(op + 3*HH)   = make_float2(x.x - a.x, x.y - a.y);
            }
        }
    }
}

// ---------------------------------------------------------------------------
extern "C" void kernel_launch(void* const* d_in, const int* in_sizes, int n_in,
                              void* d_out, int out_size)
{
    (void)in_sizes; (void)n_in; (void)out_size;
    const float* x1   = (const float*)d_in[0];
    const float* x2   = (const float*)d_in[1];
    const int*   x2m  = (const int*)d_in[3];
    const float* W    = (const float*)d_in[4];
    const float* bias = (const float*)d_in[5];
    float*       out  = (float*)d_out;

    cudaFuncSetAttribute(proj_gemm,   cudaFuncAttributeMaxDynamicSharedMemorySize, SMEM_BYTES);
    cudaFuncSetAttribute(scores_gemm, cudaFuncAttributeMaxDynamicSharedMemorySize, SMEM_BYTES);
    cudaFuncSetAttribute(att_gemm,    cudaFuncAttributeMaxDynamicSharedMemorySize, SMEM_BYTES);

    index_kernel<<<NB, 256>>>(x2m);

    pack_x1_kernel<<<(NB*LL*HH/4)/256, 256>>>(x1);
    pack_w_kernel<<<(HH*HH/4)/256, 256>>>(W);

    dim3 gXC(LL, NB);
    pack_x2c_kernel<<<gXC, 192>>>(x2);

    dim3 gT(LL/32, HH/32, NB);
    transpose_gather<<<gT, 256>>>(x2);

    dim3 gP(HH/64, (NB*LL)/128, 2);         // (12, 128, 2)
    proj_gemm<<<gP, 256, SMEM_BYTES>>>(bias);

    dim3 gS(LL/64, LL/128, NB);             // (16, 8, 16)
    scores_gemm<<<gS, 256, SMEM_BYTES>>>();

    dim3 gM(LL, NB);
    softmax_pack<<<gM, 256>>>();

    dim3 gA(HH/64, LL/128, NB);             // (12, 8, 16)
    att_gemm<<<gA, 256, SMEM_BYTES>>>(x1, out);
}

// round 16
// speedup vs baseline: 1.5336x; 1.0065x over previous
#include <cuda_runtime.h>
#include <cuda_bf16.h>
#include <cuda_fp16.h>
#include <math.h>
#include <stdint.h>

#define NB 16
#define LL 1024
#define HH 768
#define OUTW (4*HH)
#define KCP (HH/32)   // 24 hi/lo k32-chunks for proj/scores operands
#define KCS (LL/64)   // 16 fp16 k64-chunks (max) for att operands
#define KVS (LL/64)

// ---------------------------------------------------------------------------
// Packed scratch
// ---------------------------------------------------------------------------
__device__ uint4 g_x1p[(size_t)NB*LL*KCP*8];   // 48 MB hi/lo
__device__ uint4 g_x2p[(size_t)NB*LL*KCP*8];   // 48 MB hi/lo (COMPACT rows)
__device__ uint4 g_wp [(size_t)HH*KCP*8];      // 2.25 MB hi/lo
__device__ uint4 g_xpp[(size_t)NB*LL*KCP*8];   // 48 MB hi/lo
__device__ uint4 g_ypp[(size_t)NB*LL*KCP*8];   // 48 MB hi/lo (COMPACT rows)
__device__ uint4 g_ap [(size_t)NB*LL*KCS*8];   // 32 MB fp16 alpha (compact j')
__device__ uint4 g_vtp[(size_t)NB*HH*KVS*8];   // 24 MB fp16 x2^T (compact j')
__device__ float g_sc [(size_t)NB*LL*LL];      // 64 MB scores fp32 (compact cols)
__device__ int   g_jidx[NB][LL];               // compacted j index per batch
__device__ int   g_cnt [NB];                   // unmasked count per batch

// ---------------------------------------------------------------------------
__device__ __forceinline__ uint32_t smem_u32(const void* p) {
    uint32_t a;
    asm("{ .reg .u64 t; cvta.to.shared.u64 t, %1; cvt.u32.u64 %0, t; }"
        : "=r"(a) : "l"(p));
    return a;
}

__device__ __forceinline__ void split4(float4 v, uint32_t& h0, uint32_t& h1,
                                       uint32_t& l0, uint32_t& l1) {
    __nv_bfloat162 a = __floats2bfloat162_rn(v.x, v.y);
    __nv_bfloat162 b = __floats2bfloat162_rn(v.z, v.w);
    float2 fa = __bfloat1622float2(a), fb = __bfloat1622float2(b);
    __nv_bfloat162 c = __floats2bfloat162_rn(v.x - fa.x, v.y - fa.y);
    __nv_bfloat162 d = __floats2bfloat162_rn(v.z - fb.x, v.w - fb.y);
    h0 = *reinterpret_cast<uint32_t*>(&a);
    h1 = *reinterpret_cast<uint32_t*>(&b);
    l0 = *reinterpret_cast<uint32_t*>(&c);
    l1 = *reinterpret_cast<uint32_t*>(&d);
}

#define CP16(dst, src) \
    asm volatile("cp.async.cg.shared.global [%0], [%1], 16;" :: "r"(dst), "l"(src))
#define CPCOMMIT() asm volatile("cp.async.commit_group;" ::: "memory")
#define CPWAIT1()  asm volatile("cp.async.wait_group 1;" ::: "memory")

#define LDSM4(r0,r1,r2,r3,addr) \
    asm volatile("ldmatrix.sync.aligned.m8n8.x4.shared.b16 {%0,%1,%2,%3}, [%4];" \
                 : "=r"(r0),"=r"(r1),"=r"(r2),"=r"(r3) : "r"(addr))

#define MMA(c,a0,a1,a2,a3,b0,b1) \
    asm volatile("mma.sync.aligned.m16n8k16.row.col.f32.bf16.bf16.f32 " \
                 "{%0,%1,%2,%3}, {%4,%5,%6,%7}, {%8,%9}, {%0,%1,%2,%3};" \
                 : "+f"((c)[0]),"+f"((c)[1]),"+f"((c)[2]),"+f"((c)[3]) \
                 : "r"(a0),"r"(a1),"r"(a2),"r"(a3),"r"(b0),"r"(b1))

#define MMA_H(c,a0,a1,a2,a3,b0,b1) \
    asm volatile("mma.sync.aligned.m16n8k16.row.col.f32.f16.f16.f32 " \
                 "{%0,%1,%2,%3}, {%4,%5,%6,%7}, {%8,%9}, {%0,%1,%2,%3};" \
                 : "+f"((c)[0]),"+f"((c)[1]),"+f"((c)[2]),"+f"((c)[3]) \
                 : "r"(a0),"r"(a1),"r"(a2),"r"(a3),"r"(b0),"r"(b1))

// CTA tile 128x64: stage = A 16KB + B 8KB
#define STAGE_BYTES 24576u
#define SMEM_BYTES  (3 * 24576)

// ---------------------------------------------------------------------------
// 3-pass split-bf16 mainloop. a_tsrc = THIS thread's A source (row + seg resolved).
// ---------------------------------------------------------------------------
__device__ __forceinline__ void gemm_main3(const uint8_t* __restrict__ a_tsrc,
                                           const uint8_t* __restrict__ Bp,
                                           int KC, char* smem, float (&c)[2][4][4])
{
    const int tid  = threadIdx.x;
    const int lane = tid & 31, wid = tid >> 5;
    const int wm = wid >> 1, wn = wid & 1;
    const uint32_t sb = smem_u32(smem);

    #pragma unroll
    for (int mi = 0; mi < 2; mi++)
        #pragma unroll
        for (int ni = 0; ni < 4; ni++)
            #pragma unroll
            for (int q = 0; q < 4; q++) c[mi][ni][q] = 0.f;

    const int ar = tid >> 1;
    const int as = (tid & 1) * 4;
    uint32_t dswA[4];
    #pragma unroll
    for (int i = 0; i < 4; i++)
        dswA[i] = (uint32_t)(ar * 128 + (((as + i) * 16) ^ ((ar & 7) << 4)));
    const int br = tid >> 2;
    const int bs = (tid & 3) * 2;
    const uint8_t* bsrc = Bp + (size_t)br * KC * 128 + bs * 16;
    uint32_t dswB[2];
    #pragma unroll
    for (int i = 0; i < 2; i++)
        dswB[i] = (uint32_t)(br * 128 + (((bs + i) * 16) ^ ((br & 7) << 4)));

    auto issue = [&](int kt, int st) {
        const uint32_t base = sb + (uint32_t)st * STAGE_BYTES;
        const uint8_t* a = a_tsrc + (size_t)kt * 128;
        const uint8_t* b = bsrc + (size_t)kt * 128;
        #pragma unroll
        for (int i = 0; i < 4; i++) CP16(base + dswA[i], a + i * 16);
        #pragma unroll
        for (int i = 0; i < 2; i++) CP16(base + 16384u + dswB[i], b + i * 16);
    };

    issue(0, 0); CPCOMMIT();
    issue(1, 1); CPCOMMIT();

    const int l15  = lane & 15;
    const int lseg = (lane >> 4) * 16;

    for (int kt = 0; kt < KC; kt++) {
        const int st = kt % 3;
        CPWAIT1();
        __syncthreads();
        if (kt + 2 < KC) issue(kt + 2, (kt + 2) % 3);
        CPCOMMIT();

        const uint32_t Ab = sb + (uint32_t)st * STAGE_BYTES;
        const uint32_t Bb = Ab + 16384u;

        #pragma unroll
        for (int ks = 0; ks < 2; ks++) {
            const int cbh = ks * 32 + lseg;
            uint32_t a[2][4], bh[4][2], bl[4][2];
            #pragma unroll
            for (int mi = 0; mi < 2; mi++) {
                int row = wm * 32 + mi * 16 + l15;
                LDSM4(a[mi][0], a[mi][1], a[mi][2], a[mi][3],
                      Ab + row * 128 + (cbh ^ ((row & 7) << 4)));
            }
            #pragma unroll
            for (int g = 0; g < 2; g++) {
                int row = wn * 32 + g * 16 + l15;
                uint32_t xr = (row & 7) << 4;
                uint32_t r0, r1, r2, r3;
                LDSM4(r0, r1, r2, r3, Bb + row * 128 + (cbh ^ xr));
                bh[2*g][0] = r0; bh[2*g][1] = r2;
                bh[2*g+1][0] = r1; bh[2*g+1][1] = r3;
                LDSM4(r0, r1, r2, r3, Bb + row * 128 + ((cbh + 64) ^ xr));
                bl[2*g][0] = r0; bl[2*g][1] = r2;
                bl[2*g+1][0] = r1; bl[2*g+1][1] = r3;
            }
            #pragma unroll
            for (int mi = 0; mi < 2; mi++)
                #pragma unroll
                for (int ni = 0; ni < 4; ni++)
                    MMA(c[mi][ni], a[mi][0], a[mi][1], a[mi][2], a[mi][3],
                        bh[ni][0], bh[ni][1]);
            #pragma unroll
            for (int mi = 0; mi < 2; mi++)
                #pragma unroll
                for (int ni = 0; ni < 4; ni++)
                    MMA(c[mi][ni], a[mi][0], a[mi][1], a[mi][2], a[mi][3],
                        bl[ni][0], bl[ni][1]);
            #pragma unroll
            for (int mi = 0; mi < 2; mi++) {
                int row = wm * 32 + mi * 16 + l15;
                LDSM4(a[mi][0], a[mi][1], a[mi][2], a[mi][3],
                      Ab + row * 128 + ((cbh + 64) ^ ((row & 7) << 4)));
            }
            #pragma unroll
            for (int mi = 0; mi < 2; mi++)
                #pragma unroll
                for (int ni = 0; ni < 4; ni++)
                    MMA(c[mi][ni], a[mi][0], a[mi][1], a[mi][2], a[mi][3],
                        bh[ni][0], bh[ni][1]);
        }
    }
}

// ---------------------------------------------------------------------------
// Single-pass fp16 mainloop (att), runtime KC
// ---------------------------------------------------------------------------
__device__ __forceinline__ void gemm_main1(const uint8_t* __restrict__ Ap,
                                           const uint8_t* __restrict__ Bp,
                                           int KC, char* smem, float (&c)[2][4][4])
{
    const int tid  = threadIdx.x;
    const int lane = tid & 31, wid = tid >> 5;
    const int wm = wid >> 1, wn = wid & 1;
    const uint32_t sb = smem_u32(smem);

    #pragma unroll
    for (int mi = 0; mi < 2; mi++)
        #pragma unroll
        for (int ni = 0; ni < 4; ni++)
            #pragma unroll
            for (int q = 0; q < 4; q++) c[mi][ni][q] = 0.f;

    const int ar = tid >> 1;
    const int as = (tid & 1) * 4;
    const uint8_t* asrc = Ap + (size_t)ar * KCS * 128 + as * 16;
    uint32_t dswA[4];
    #pragma unroll
    for (int i = 0; i < 4; i++)
        dswA[i] = (uint32_t)(ar * 128 + (((as + i) * 16) ^ ((ar & 7) << 4)));
    const int br = tid >> 2;
    const int bs = (tid & 3) * 2;
    const uint8_t* bsrc = Bp + (size_t)br * KVS * 128 + bs * 16;
    uint32_t dswB[2];
    #pragma unroll
    for (int i = 0; i < 2; i++)
        dswB[i] = (uint32_t)(br * 128 + (((bs + i) * 16) ^ ((br & 7) << 4)));

    auto issue = [&](int kt, int st) {
        const uint32_t base = sb + (uint32_t)st * STAGE_BYTES;
        const uint8_t* a = asrc + (size_t)kt * 128;
        const uint8_t* b = bsrc + (size_t)kt * 128;
        #pragma unroll
        for (int i = 0; i < 4; i++) CP16(base + dswA[i], a + i * 16);
        #pragma unroll
        for (int i = 0; i < 2; i++) CP16(base + 16384u + dswB[i], b + i * 16);
    };

    issue(0, 0); CPCOMMIT();
    issue(1, 1); CPCOMMIT();

    const int l15  = lane & 15;
    const int lseg = (lane >> 4) * 16;

    for (int kt = 0; kt < KC; kt++) {
        const int st = kt % 3;
        CPWAIT1();
        __syncthreads();
        if (kt + 2 < KC) issue(kt + 2, (kt + 2) % 3);
        CPCOMMIT();

        const uint32_t Ab = sb + (uint32_t)st * STAGE_BYTES;
        const uint32_t Bb = Ab + 16384u;

        #pragma unroll
        for (int ks = 0; ks < 4; ks++) {
            const int cb = ks * 32 + lseg;
            uint32_t a[2][4], bh[4][2];
            #pragma unroll
            for (int mi = 0; mi < 2; mi++) {
                int row = wm * 32 + mi * 16 + l15;
                LDSM4(a[mi][0], a[mi][1], a[mi][2], a[mi][3],
                      Ab + row * 128 + (cb ^ ((row & 7) << 4)));
            }
            #pragma unroll
            for (int g = 0; g < 2; g++) {
                int row = wn * 32 + g * 16 + l15;
                uint32_t xr = (row & 7) << 4;
                uint32_t r0, r1, r2, r3;
                LDSM4(r0, r1, r2, r3, Bb + row * 128 + (cb ^ xr));
                bh[2*g][0] = r0; bh[2*g][1] = r2;
                bh[2*g+1][0] = r1; bh[2*g+1][1] = r3;
            }
            #pragma unroll
            for (int mi = 0; mi < 2; mi++)
                #pragma unroll
                for (int ni = 0; ni < 4; ni++)
                    MMA_H(c[mi][ni], a[mi][0], a[mi][1], a[mi][2], a[mi][3],
                          bh[ni][0], bh[ni][1]);
        }
    }
}

// ---------------------------------------------------------------------------
// Fused prep: blocks [0,NB) = index, [NB,NB+576) = pack_w, rest = pack_x1
// ---------------------------------------------------------------------------
#define PW_BLOCKS ((HH*HH/4)/256)            // 576
#define PX1_BLOCKS ((NB*LL*HH/4)/256)        // 12288
__global__ __launch_bounds__(256) void prep_kernel(const int* __restrict__ mask2,
                                                   const float* __restrict__ W,
                                                   const float* __restrict__ x1)
{
    const int bx = blockIdx.x;
    const int tid = threadIdx.x;

    if (bx < NB) {
        // ---- index: compact unmasked j for batch bx ----
        const int b = bx;
        __shared__ int wsum[8];
        int4 m = *(const int4*)(mask2 + (size_t)b * LL + tid * 4);
        int keep[4] = { m.x == 0, m.y == 0, m.z == 0, m.w == 0 };
        int cnt4 = keep[0] + keep[1] + keep[2] + keep[3];
        const int lane = tid & 31, wid = tid >> 5;
        int s = cnt4;
        #pragma unroll
        for (int o = 1; o < 32; o <<= 1) {
            int v = __shfl_up_sync(0xffffffffu, s, o);
            if (lane >= o) s += v;
        }
        if (lane == 31) wsum[wid] = s;
        __syncthreads();
        int wb = 0;
        for (int w = 0; w < wid; w++) wb += wsum[w];
        int base = wb + s - cnt4;
        const int j0 = tid * 4;
        #pragma unroll
        for (int q = 0; q < 4; q++)
            if (keep[q]) g_jidx[b][base++] = j0 + q;
        if (tid == 255) g_cnt[b] = wb + s;
    } else if (bx < NB + PW_BLOCKS) {
        // ---- pack_w ----
        size_t id = (size_t)(bx - NB) * 256 + tid;
        size_t k4 = id * 4;
        int row = (int)(k4 / HH);
        int k   = (int)(k4 - (size_t)row * HH);
        float4 v = *(const float4*)(W + k4);
        uint32_t h0, h1, l0, l1;
        split4(v, h0, h1, l0, l1);
        uint32_t* d = (uint32_t*)g_wp + ((size_t)row * KCP + (k >> 5)) * 32 + ((k & 31) >> 1);
        *(uint2*)d        = make_uint2(h0, h1);
        *(uint2*)(d + 16) = make_uint2(l0, l1);
    } else {
        // ---- pack_x1 ----
        size_t id = (size_t)(bx - NB - PW_BLOCKS) * 256 + tid;
        size_t k4 = id * 4;
        int row = (int)(k4 / HH);
        int k   = (int)(k4 - (size_t)row * HH);
        float4 v = *(const float4*)(x1 + k4);
        uint32_t h0, h1, l0, l1;
        split4(v, h0, h1, l0, l1);
        uint32_t* d = (uint32_t*)g_x1p + ((size_t)row * KCP + (k >> 5)) * 32 + ((k & 31) >> 1);
        *(uint2*)d        = make_uint2(h0, h1);
        *(uint2*)(d + 16) = make_uint2(l0, l1);
    }
}

// COMPACT x2 pack: row c of g_x2p = split(x2[jidx[min(c,cnt-1)]]) for c < pad128(cnt)
__global__ __launch_bounds__(192) void pack_x2c_kernel(const float* __restrict__ x2)
{
    const int b = blockIdx.y;
    const int c = blockIdx.x;
    const int cnt = g_cnt[b];
    if (c >= ((cnt + 127) & ~127)) return;
    const int j = g_jidx[b][c < cnt ? c : cnt - 1];
    const int tid = threadIdx.x;
    const int k4 = tid * 4;
    float4 v = *(const float4*)(x2 + ((size_t)b * LL + j) * HH + k4);
    uint32_t h0, h1, l0, l1;
    split4(v, h0, h1, l0, l1);
    uint32_t* d = (uint32_t*)g_x2p
                + (((size_t)b * LL + c) * KCP + (k4 >> 5)) * 32 + ((k4 & 31) >> 1);
    *(uint2*)d        = make_uint2(h0, h1);
    *(uint2*)(d + 16) = make_uint2(l0, l1);
}

// Gathered transpose: vtp[h][c] = fp16(x2[jidx[c]][h]) for compact c
__global__ __launch_bounds__(256) void transpose_gather(const float* __restrict__ X2)
{
    __shared__ float t[32][33];
    const int b  = blockIdx.z;
    const int c0 = blockIdx.x * 32;
    const int h0 = blockIdx.y * 32;
    const int cnt = g_cnt[b];
    if (c0 >= ((cnt + 63) & ~63)) return;
    const int tid = threadIdx.x;
    const int tx = tid & 31, ty = tid >> 5;
    #pragma unroll
    for (int i = 0; i < 4; i++) {
        int cc = c0 + ty + i * 8;
        int j = g_jidx[b][cc < cnt ? cc : cnt - 1];
        t[ty + i * 8][tx] = X2[((size_t)b * LL + j) * HH + h0 + tx];
    }
    __syncthreads();
    const int oy = tid >> 3;
    const int ox = (tid & 7) * 4;
    __half2 p01 = __float22half2_rn(make_float2(t[ox][oy],   t[ox+1][oy]));
    __half2 p23 = __float22half2_rn(make_float2(t[ox+2][oy], t[ox+3][oy]));
    const size_t row = (size_t)b * HH + h0 + oy;
    const int chunk = blockIdx.x >> 1;
    uint32_t* d = (uint32_t*)g_vtp + (row * KVS + chunk) * 32
                + (blockIdx.x & 1) * 16 + (ox >> 1);
    *(uint2*)d = make_uint2(*reinterpret_cast<uint32_t*>(&p01),
                            *reinterpret_cast<uint32_t*>(&p23));
}

// ---------------------------------------------------------------------------
// GEMM kernels
// ---------------------------------------------------------------------------
__global__ __launch_bounds__(256, 3) void proj_gemm(const float* __restrict__ bias)
{
    extern __shared__ char smem[];
    const int z  = blockIdx.z;
    const int y  = blockIdx.y;
    const int m0 = y * 128;
    const int n0 = blockIdx.x * 64;
    const int tid = threadIdx.x;

    if (z == 1) {
        const int b   = y >> 3;
        if (((y & 7) * 128) >= g_cnt[b]) return;
    }
    const uint8_t* a_tsrc = (const uint8_t*)(z ? g_x2p : g_x1p)
        + ((size_t)(m0 + (tid >> 1)) * KCP) * 128 + (tid & 1) * 64;
    const uint8_t* Bp = (const uint8_t*)g_wp + (size_t)n0 * KCP * 128;

    float c[2][4][4];
    gemm_main3(a_tsrc, Bp, KCP, smem, c);

    __syncthreads();
    const int lane = tid & 31, wid = tid >> 5;
    const int wm = wid >> 1, wn = wid & 1;
    #pragma unroll
    for (int mi = 0; mi < 2; mi++) {
        #pragma unroll
        for (int ni = 0; ni < 4; ni++) {
            const int cc = wn * 32 + ni * 8 + 2 * (lane & 3);
            const int gc = n0 + cc;
            const float b0 = bias[gc], b1 = bias[gc + 1];
            #pragma unroll
            for (int hrow = 0; hrow < 2; hrow++) {
                const int r = wm * 32 + mi * 16 + (lane >> 2) + 8 * hrow;
                float v0 = fmaxf(c[mi][ni][2*hrow + 0] + b0, 0.f);
                float v1 = fmaxf(c[mi][ni][2*hrow + 1] + b1, 0.f);
                __nv_bfloat162 h = __floats2bfloat162_rn(v0, v1);
                float2 f = __bfloat1622float2(h);
                __nv_bfloat162 l = __floats2bfloat162_rn(v0 - f.x, v1 - f.y);
                uint32_t off = (uint32_t)(r * 256 + (cc >> 5) * 128 + (cc & 31) * 2);
                *(uint32_t*)(smem + off)      = *reinterpret_cast<uint32_t*>(&h);
                *(uint32_t*)(smem + off + 64) = *reinterpret_cast<uint32_t*>(&l);
            }
        }
    }
    __syncthreads();
    uint4* dst = (z ? g_ypp : g_xpp);
    const uint4* ssrc = (const uint4*)smem;
    #pragma unroll
    for (int i = 0; i < 8; i++) {
        int idx = i * 256 + tid;
        int r   = idx >> 4;
        int ci  = (idx >> 3) & 1;
        int seg = idx & 7;
        dst[((size_t)(m0 + r) * KCP + (n0 >> 5) + ci) * 8 + seg] = ssrc[idx];
    }
}

__global__ __launch_bounds__(256, 3) void scores_gemm()
{
    extern __shared__ char smem[];
    const int b  = blockIdx.z;
    const int m0 = blockIdx.y * 128;
    const int n0 = blockIdx.x * 64;
    if (n0 >= g_cnt[b]) return;
    const int tid = threadIdx.x;
    const uint8_t* a_tsrc = (const uint8_t*)g_xpp
        + ((size_t)(b * LL + m0 + (tid >> 1)) * KCP) * 128 + (tid & 1) * 64;
    const uint8_t* Bp = (const uint8_t*)g_ypp + (size_t)(b * LL + n0) * KCP * 128;

    float c[2][4][4];
    gemm_main3(a_tsrc, Bp, KCP, smem, c);

    const int lane = tid & 31, wid = tid >> 5;
    const int wm = wid >> 1, wn = wid & 1;
    float* C = g_sc + ((size_t)b * LL + m0) * LL + n0;
    #pragma unroll
    for (int mi = 0; mi < 2; mi++) {
        const int r0 = wm * 32 + mi * 16 + (lane >> 2);
        #pragma unroll
        for (int ni = 0; ni < 4; ni++) {
            const int cc = wn * 32 + ni * 8 + 2 * (lane & 3);
            *(float2*)(C + (size_t)r0 * LL + cc)       = make_float2(c[mi][ni][0], c[mi][ni][1]);
            *(float2*)(C + (size_t)(r0 + 8) * LL + cc) = make_float2(c[mi][ni][2], c[mi][ni][3]);
        }
    }
}

// softmax over compacted columns; loads and alpha-writes restricted to live region
__global__ __launch_bounds__(256) void softmax_pack()
{
    const int b = blockIdx.y, i = blockIdx.x, tid = threadIdx.x;
    const float* row = g_sc + ((size_t)b * LL + i) * LL;
    const int cnt = g_cnt[b];
    const int KCb = (cnt + 63) >> 6;

    const int j0 = tid * 4;
    float4 s = make_float4(0.f, 0.f, 0.f, 0.f);
    if (j0 < cnt) s = *(const float4*)(row + j0);
    float v[4];
    v[0] = (j0 + 0 < cnt) ? s.x : -INFINITY;
    v[1] = (j0 + 1 < cnt) ? s.y : -INFINITY;
    v[2] = (j0 + 2 < cnt) ? s.z : -INFINITY;
    v[3] = (j0 + 3 < cnt) ? s.w : -INFINITY;

    float mx = fmaxf(fmaxf(v[0], v[1]), fmaxf(v[2], v[3]));
    #pragma unroll
    for (int o = 16; o > 0; o >>= 1) mx = fmaxf(mx, __shfl_xor_sync(0xffffffffu, mx, o));

    __shared__ float red[8];
    if ((tid & 31) == 0) red[tid >> 5] = mx;
    __syncthreads();
    float bm = red[0];
    #pragma unroll
    for (int w = 1; w < 8; w++) bm = fmaxf(bm, red[w]);

    float e[4];
    float sum = 0.f;
    #pragma unroll
    for (int q = 0; q < 4; q++) { e[q] = expf(v[q] - bm); sum += e[q]; }
    #pragma unroll
    for (int o = 16; o > 0; o >>= 1) sum += __shfl_xor_sync(0xffffffffu, sum, o);

    __syncthreads();
    if ((tid & 31) == 0) red[tid >> 5] = sum;
    __syncthreads();
    float bs = 0.f;
    #pragma unroll
    for (int w = 0; w < 8; w++) bs += red[w];
    const float inv = 1.0f / bs;

    const int chunk = tid >> 4;
    if (chunk < KCb) {
        __half2 p01 = __float22half2_rn(make_float2(e[0]*inv, e[1]*inv));
        __half2 p23 = __float22half2_rn(make_float2(e[2]*inv, e[3]*inv));
        uint32_t* d = (uint32_t*)g_ap + (((size_t)b * LL + i) * KCS + chunk) * 32
                    + (tid & 15) * 2;
        *(uint2*)d = make_uint2(*reinterpret_cast<uint32_t*>(&p01),
                                *reinterpret_cast<uint32_t*>(&p23));
    }
}

// att with per-batch runtime K = ceil(cnt/64) chunks
__global__ __launch_bounds__(256, 3) void att_gemm(const float* __restrict__ X1,
                                                   float* __restrict__ OUT)
{
    extern __shared__ char smem[];
    const int b  = blockIdx.z;
    const int m0 = blockIdx.y * 128;
    const int n0 = blockIdx.x * 64;
    const int KCb = (g_cnt[b] + 63) >> 6;
    const uint8_t* Ap = (const uint8_t*)g_ap  + (size_t)(b * LL + m0) * KCS * 128;
    const uint8_t* Bp = (const uint8_t*)g_vtp + (size_t)(b * HH + n0) * KVS * 128;

    float c[2][4][4];
    gemm_main1(Ap, Bp, KCb, smem, c);

    const int lane = threadIdx.x & 31, wid = threadIdx.x >> 5;
    const int wm = wid >> 1, wn = wid & 1;
    #pragma unroll
    for (int mi = 0; mi < 2; mi++) {
        const int r0 = m0 + wm * 32 + mi * 16 + (lane >> 2);
        #pragma unroll
        for (int ni = 0; ni < 4; ni++) {
            const int cc = wn * 32 + ni * 8 + 2 * (lane & 3);
            #pragma unroll
            for (int hrow = 0; hrow < 2; hrow++) {
                const int gr = r0 + 8 * hrow;
                float2 a = make_float2(c[mi][ni][2*hrow + 0], c[mi][ni][2*hrow + 1]);
                const float* xp = X1  + ((size_t)b * LL + gr) * HH   + n0 + cc;
                float*       op = OUT + ((size_t)b * LL + gr) * OUTW + n0 + cc;
                float2 x = *(const float2*)xp;
                *(float2*)(op)          = x;
                *(float2*)(op + HH)     = a;
                *(float2*)(op + 2*HH)   = make_float2(x.x * a.x, x.y * a.y);
                *(float2*)(op + 3*HH)   = make_float2(x.x - a.x, x.y - a.y);
            }
        }
    }
}

// ---------------------------------------------------------------------------
extern "C" void kernel_launch(void* const* d_in, const int* in_sizes, int n_in,
                              void* d_out, int out_size)
{
    (void)in_sizes; (void)n_in; (void)out_size;
    const float* x1   = (const float*)d_in[0];
    const float* x2   = (const float*)d_in[1];
    const int*   x2m  = (const int*)d_in[3];
    const float* W    = (const float*)d_in[4];
    const float* bias = (const float*)d_in[5];
    float*       out  = (float*)d_out;

    cudaFuncSetAttribute(proj_gemm,   cudaFuncAttributeMaxDynamicSharedMemorySize, SMEM_BYTES);
    cudaFuncSetAttribute(scores_gemm, cudaFuncAttributeMaxDynamicSharedMemorySize, SMEM_BYTES);
    cudaFuncSetAttribute(att_gemm,    cudaFuncAttributeMaxDynamicSharedMemorySize, SMEM_BYTES);

    prep_kernel<<<NB + PW_BLOCKS + PX1_BLOCKS, 256>>>(x2m, W, x1);  // 12880 blocks

    dim3 gXC(LL, NB);
    pack_x2c_kernel<<<gXC, 192>>>(x2);

    dim3 gT(LL/32, HH/32, NB);
    transpose_gather<<<gT, 256>>>(x2);

    dim3 gP(HH/64, (NB*LL)/128, 2);         // (12, 128, 2)
    proj_gemm<<<gP, 256, SMEM_BYTES>>>(bias);

    dim3 gS(LL/64, LL/128, NB);             // (16, 8, 16)
    scores_gemm<<<gS, 256, SMEM_BYTES>>>();

    dim3 gM(LL, NB);
    softmax_pack<<<gM, 256>>>();

    dim3 gA(HH/64, LL/128, NB);             // (12, 8, 16)
    att_gemm<<<gA, 256, SMEM_BYTES>>>(x1, out);
}

// round 17
// speedup vs baseline: 1.5542x; 1.0135x over previous
#include <cuda_runtime.h>
#include <cuda_bf16.h>
#include <cuda_fp16.h>
#include <math.h>
#include <stdint.h>

#define NB 16
#define LL 1024
#define HH 768
#define OUTW (4*HH)
#define KCP (HH/32)   // 24 hi/lo k32-chunks for proj/scores operands
#define KCS (LL/64)   // 16 fp16 k64-chunks (max) for att operands
#define KVS (LL/64)

// ---------------------------------------------------------------------------
// Packed scratch
// ---------------------------------------------------------------------------
__device__ uint4 g_x1p[(size_t)NB*LL*KCP*8];   // 48 MB hi/lo
__device__ uint4 g_x2p[(size_t)NB*LL*KCP*8];   // 48 MB hi/lo (COMPACT rows)
__device__ uint4 g_wp [(size_t)HH*KCP*8];      // 2.25 MB hi/lo
__device__ uint4 g_xpp[(size_t)NB*LL*KCP*8];   // 48 MB hi/lo
__device__ uint4 g_ypp[(size_t)NB*LL*KCP*8];   // 48 MB hi/lo (COMPACT rows)
__device__ uint4 g_ap [(size_t)NB*LL*KCS*8];   // 32 MB fp16 alpha (compact j')
__device__ uint4 g_vtp[(size_t)NB*HH*KVS*8];   // 24 MB fp16 x2^T (compact j')
__device__ float g_sc [(size_t)NB*LL*LL];      // 64 MB scores fp32 (compact cols)
__device__ int   g_jidx[NB][LL];               // compacted j index per batch
__device__ int   g_cnt [NB];                   // unmasked count per batch

// ---------------------------------------------------------------------------
__device__ __forceinline__ uint32_t smem_u32(const void* p) {
    uint32_t a;
    asm("{ .reg .u64 t; cvta.to.shared.u64 t, %1; cvt.u32.u64 %0, t; }"
        : "=r"(a) : "l"(p));
    return a;
}

__device__ __forceinline__ void split4(float4 v, uint32_t& h0, uint32_t& h1,
                                       uint32_t& l0, uint32_t& l1) {
    __nv_bfloat162 a = __floats2bfloat162_rn(v.x, v.y);
    __nv_bfloat162 b = __floats2bfloat162_rn(v.z, v.w);
    float2 fa = __bfloat1622float2(a), fb = __bfloat1622float2(b);
    __nv_bfloat162 c = __floats2bfloat162_rn(v.x - fa.x, v.y - fa.y);
    __nv_bfloat162 d = __floats2bfloat162_rn(v.z - fb.x, v.w - fb.y);
    h0 = *reinterpret_cast<uint32_t*>(&a);
    h1 = *reinterpret_cast<uint32_t*>(&b);
    l0 = *reinterpret_cast<uint32_t*>(&c);
    l1 = *reinterpret_cast<uint32_t*>(&d);
}

#define CP16(dst, src) \
    asm volatile("cp.async.cg.shared.global [%0], [%1], 16;" :: "r"(dst), "l"(src))
#define CPCOMMIT() asm volatile("cp.async.commit_group;" ::: "memory")
#define CPWAIT1()  asm volatile("cp.async.wait_group 1;" ::: "memory")

#define LDSM4(r0,r1,r2,r3,addr) \
    asm volatile("ldmatrix.sync.aligned.m8n8.x4.shared.b16 {%0,%1,%2,%3}, [%4];" \
                 : "=r"(r0),"=r"(r1),"=r"(r2),"=r"(r3) : "r"(addr))

#define MMA(c,a0,a1,a2,a3,b0,b1) \
    asm volatile("mma.sync.aligned.m16n8k16.row.col.f32.bf16.bf16.f32 " \
                 "{%0,%1,%2,%3}, {%4,%5,%6,%7}, {%8,%9}, {%0,%1,%2,%3};" \
                 : "+f"((c)[0]),"+f"((c)[1]),"+f"((c)[2]),"+f"((c)[3]) \
                 : "r"(a0),"r"(a1),"r"(a2),"r"(a3),"r"(b0),"r"(b1))

#define MMA_H(c,a0,a1,a2,a3,b0,b1) \
    asm volatile("mma.sync.aligned.m16n8k16.row.col.f32.f16.f16.f32 " \
                 "{%0,%1,%2,%3}, {%4,%5,%6,%7}, {%8,%9}, {%0,%1,%2,%3};" \
                 : "+f"((c)[0]),"+f"((c)[1]),"+f"((c)[2]),"+f"((c)[3]) \
                 : "r"(a0),"r"(a1),"r"(a2),"r"(a3),"r"(b0),"r"(b1))

// CTA tile 128x64: stage = A 16KB + B 8KB
#define STAGE_BYTES 24576u
#define SMEM_BYTES  (3 * 24576)

// ---------------------------------------------------------------------------
// 3-pass split-bf16 mainloop. a_tsrc = THIS thread's A source (row + seg resolved).
// ---------------------------------------------------------------------------
__device__ __forceinline__ void gemm_main3(const uint8_t* __restrict__ a_tsrc,
                                           const uint8_t* __restrict__ Bp,
                                           int KC, char* smem, float (&c)[2][4][4])
{
    const int tid  = threadIdx.x;
    const int lane = tid & 31, wid = tid >> 5;
    const int wm = wid >> 1, wn = wid & 1;
    const uint32_t sb = smem_u32(smem);

    #pragma unroll
    for (int mi = 0; mi < 2; mi++)
        #pragma unroll
        for (int ni = 0; ni < 4; ni++)
            #pragma unroll
            for (int q = 0; q < 4; q++) c[mi][ni][q] = 0.f;

    const int ar = tid >> 1;
    const int as = (tid & 1) * 4;
    uint32_t dswA[4];
    #pragma unroll
    for (int i = 0; i < 4; i++)
        dswA[i] = (uint32_t)(ar * 128 + (((as + i) * 16) ^ ((ar & 7) << 4)));
    const int br = tid >> 2;
    const int bs = (tid & 3) * 2;
    const uint8_t* bsrc = Bp + (size_t)br * KC * 128 + bs * 16;
    uint32_t dswB[2];
    #pragma unroll
    for (int i = 0; i < 2; i++)
        dswB[i] = (uint32_t)(br * 128 + (((bs + i) * 16) ^ ((br & 7) << 4)));

    auto issue = [&](int kt, int st) {
        const uint32_t base = sb + (uint32_t)st * STAGE_BYTES;
        const uint8_t* a = a_tsrc + (size_t)kt * 128;
        const uint8_t* b = bsrc + (size_t)kt * 128;
        #pragma unroll
        for (int i = 0; i < 4; i++) CP16(base + dswA[i], a + i * 16);
        #pragma unroll
        for (int i = 0; i < 2; i++) CP16(base + 16384u + dswB[i], b + i * 16);
    };

    issue(0, 0); CPCOMMIT();
    issue(1, 1); CPCOMMIT();

    const int l15  = lane & 15;
    const int lseg = (lane >> 4) * 16;

    for (int kt = 0; kt < KC; kt++) {
        const int st = kt % 3;
        CPWAIT1();
        __syncthreads();
        if (kt + 2 < KC) issue(kt + 2, (kt + 2) % 3);
        CPCOMMIT();

        const uint32_t Ab = sb + (uint32_t)st * STAGE_BYTES;
        const uint32_t Bb = Ab + 16384u;

        #pragma unroll
        for (int ks = 0; ks < 2; ks++) {
            const int cbh = ks * 32 + lseg;
            uint32_t a[2][4], bh[4][2], bl[4][2];
            #pragma unroll
            for (int mi = 0; mi < 2; mi++) {
                int row = wm * 32 + mi * 16 + l15;
                LDSM4(a[mi][0], a[mi][1], a[mi][2], a[mi][3],
                      Ab + row * 128 + (cbh ^ ((row & 7) << 4)));
            }
            #pragma unroll
            for (int g = 0; g < 2; g++) {
                int row = wn * 32 + g * 16 + l15;
                uint32_t xr = (row & 7) << 4;
                uint32_t r0, r1, r2, r3;
                LDSM4(r0, r1, r2, r3, Bb + row * 128 + (cbh ^ xr));
                bh[2*g][0] = r0; bh[2*g][1] = r2;
                bh[2*g+1][0] = r1; bh[2*g+1][1] = r3;
                LDSM4(r0, r1, r2, r3, Bb + row * 128 + ((cbh + 64) ^ xr));
                bl[2*g][0] = r0; bl[2*g][1] = r2;
                bl[2*g+1][0] = r1; bl[2*g+1][1] = r3;
            }
            #pragma unroll
            for (int mi = 0; mi < 2; mi++)
                #pragma unroll
                for (int ni = 0; ni < 4; ni++)
                    MMA(c[mi][ni], a[mi][0], a[mi][1], a[mi][2], a[mi][3],
                        bh[ni][0], bh[ni][1]);
            #pragma unroll
            for (int mi = 0; mi < 2; mi++)
                #pragma unroll
                for (int ni = 0; ni < 4; ni++)
                    MMA(c[mi][ni], a[mi][0], a[mi][1], a[mi][2], a[mi][3],
                        bl[ni][0], bl[ni][1]);
            #pragma unroll
            for (int mi = 0; mi < 2; mi++) {
                int row = wm * 32 + mi * 16 + l15;
                LDSM4(a[mi][0], a[mi][1], a[mi][2], a[mi][3],
                      Ab + row * 128 + ((cbh + 64) ^ ((row & 7) << 4)));
            }
            #pragma unroll
            for (int mi = 0; mi < 2; mi++)
                #pragma unroll
                for (int ni = 0; ni < 4; ni++)
                    MMA(c[mi][ni], a[mi][0], a[mi][1], a[mi][2], a[mi][3],
                        bh[ni][0], bh[ni][1]);
        }
    }
}

// ---------------------------------------------------------------------------
// Single-pass fp16 mainloop (att), runtime KC
// ---------------------------------------------------------------------------
__device__ __forceinline__ void gemm_main1(const uint8_t* __restrict__ Ap,
                                           const uint8_t* __restrict__ Bp,
                                           int KC, char* smem, float (&c)[2][4][4])
{
    const int tid  = threadIdx.x;
    const int lane = tid & 31, wid = tid >> 5;
    const int wm = wid >> 1, wn = wid & 1;
    const uint32_t sb = smem_u32(smem);

    #pragma unroll
    for (int mi = 0; mi < 2; mi++)
        #pragma unroll
        for (int ni = 0; ni < 4; ni++)
            #pragma unroll
            for (int q = 0; q < 4; q++) c[mi][ni][q] = 0.f;

    const int ar = tid >> 1;
    const int as = (tid & 1) * 4;
    const uint8_t* asrc = Ap + (size_t)ar * KCS * 128 + as * 16;
    uint32_t dswA[4];
    #pragma unroll
    for (int i = 0; i < 4; i++)
        dswA[i] = (uint32_t)(ar * 128 + (((as + i) * 16) ^ ((ar & 7) << 4)));
    const int br = tid >> 2;
    const int bs = (tid & 3) * 2;
    const uint8_t* bsrc = Bp + (size_t)br * KVS * 128 + bs * 16;
    uint32_t dswB[2];
    #pragma unroll
    for (int i = 0; i < 2; i++)
        dswB[i] = (uint32_t)(br * 128 + (((bs + i) * 16) ^ ((br & 7) << 4)));

    auto issue = [&](int kt, int st) {
        const uint32_t base = sb + (uint32_t)st * STAGE_BYTES;
        const uint8_t* a = asrc + (size_t)kt * 128;
        const uint8_t* b = bsrc + (size_t)kt * 128;
        #pragma unroll
        for (int i = 0; i < 4; i++) CP16(base + dswA[i], a + i * 16);
        #pragma unroll
        for (int i = 0; i < 2; i++) CP16(base + 16384u + dswB[i], b + i * 16);
    };

    issue(0, 0); CPCOMMIT();
    issue(1, 1); CPCOMMIT();

    const int l15  = lane & 15;
    const int lseg = (lane >> 4) * 16;

    for (int kt = 0; kt < KC; kt++) {
        const int st = kt % 3;
        CPWAIT1();
        __syncthreads();
        if (kt + 2 < KC) issue(kt + 2, (kt + 2) % 3);
        CPCOMMIT();

        const uint32_t Ab = sb + (uint32_t)st * STAGE_BYTES;
        const uint32_t Bb = Ab + 16384u;

        #pragma unroll
        for (int ks = 0; ks < 4; ks++) {
            const int cb = ks * 32 + lseg;
            uint32_t a[2][4], bh[4][2];
            #pragma unroll
            for (int mi = 0; mi < 2; mi++) {
                int row = wm * 32 + mi * 16 + l15;
                LDSM4(a[mi][0], a[mi][1], a[mi][2], a[mi][3],
                      Ab + row * 128 + (cb ^ ((row & 7) << 4)));
            }
            #pragma unroll
            for (int g = 0; g < 2; g++) {
                int row = wn * 32 + g * 16 + l15;
                uint32_t xr = (row & 7) << 4;
                uint32_t r0, r1, r2, r3;
                LDSM4(r0, r1, r2, r3, Bb + row * 128 + (cb ^ xr));
                bh[2*g][0] = r0; bh[2*g][1] = r2;
                bh[2*g+1][0] = r1; bh[2*g+1][1] = r3;
            }
            #pragma unroll
            for (int mi = 0; mi < 2; mi++)
                #pragma unroll
                for (int ni = 0; ni < 4; ni++)
                    MMA_H(c[mi][ni], a[mi][0], a[mi][1], a[mi][2], a[mi][3],
                          bh[ni][0], bh[ni][1]);
        }
    }
}

// ---------------------------------------------------------------------------
// Fused prep: blocks [0,NB) = index, [NB,NB+576) = pack_w, rest = pack_x1
// ---------------------------------------------------------------------------
#define PW_BLOCKS ((HH*HH/4)/256)            // 576
#define PX1_BLOCKS ((NB*LL*HH/4)/256)        // 12288
__global__ __launch_bounds__(256) void prep_kernel(const int* __restrict__ mask2,
                                                   const float* __restrict__ W,
                                                   const float* __restrict__ x1)
{
    const int bx = blockIdx.x;
    const int tid = threadIdx.x;

    if (bx < NB) {
        // ---- index: compact unmasked j for batch bx ----
        const int b = bx;
        __shared__ int wsum[8];
        int4 m = *(const int4*)(mask2 + (size_t)b * LL + tid * 4);
        int keep[4] = { m.x == 0, m.y == 0, m.z == 0, m.w == 0 };
        int cnt4 = keep[0] + keep[1] + keep[2] + keep[3];
        const int lane = tid & 31, wid = tid >> 5;
        int s = cnt4;
        #pragma unroll
        for (int o = 1; o < 32; o <<= 1) {
            int v = __shfl_up_sync(0xffffffffu, s, o);
            if (lane >= o) s += v;
        }
        if (lane == 31) wsum[wid] = s;
        __syncthreads();
        int wb = 0;
        for (int w = 0; w < wid; w++) wb += wsum[w];
        int base = wb + s - cnt4;
        const int j0 = tid * 4;
        #pragma unroll
        for (int q = 0; q < 4; q++)
            if (keep[q]) g_jidx[b][base++] = j0 + q;
        if (tid == 255) g_cnt[b] = wb + s;
    } else if (bx < NB + PW_BLOCKS) {
        // ---- pack_w ----
        size_t id = (size_t)(bx - NB) * 256 + tid;
        size_t k4 = id * 4;
        int row = (int)(k4 / HH);
        int k   = (int)(k4 - (size_t)row * HH);
        float4 v = *(const float4*)(W + k4);
        uint32_t h0, h1, l0, l1;
        split4(v, h0, h1, l0, l1);
        uint32_t* d = (uint32_t*)g_wp + ((size_t)row * KCP + (k >> 5)) * 32 + ((k & 31) >> 1);
        *(uint2*)d        = make_uint2(h0, h1);
        *(uint2*)(d + 16) = make_uint2(l0, l1);
    } else {
        // ---- pack_x1 ----
        size_t id = (size_t)(bx - NB - PW_BLOCKS) * 256 + tid;
        size_t k4 = id * 4;
        int row = (int)(k4 / HH);
        int k   = (int)(k4 - (size_t)row * HH);
        float4 v = *(const float4*)(x1 + k4);
        uint32_t h0, h1, l0, l1;
        split4(v, h0, h1, l0, l1);
        uint32_t* d = (uint32_t*)g_x1p + ((size_t)row * KCP + (k >> 5)) * 32 + ((k & 31) >> 1);
        *(uint2*)d        = make_uint2(h0, h1);
        *(uint2*)(d + 16) = make_uint2(l0, l1);
    }
}

// Fused gathered transpose + compact x2 pack:
//   vtp[h][c]  = fp16(x2[jidx[c]][h])          (written for c0 < pad64(cnt))
//   x2p[c][k]  = hi/lo split(x2[jidx[c]][k])   (written for c0 < pad128(cnt))
// One gathered read of x2 through the smem tile feeds both outputs.
__global__ __launch_bounds__(256) void transpose_gather(const float* __restrict__ X2)
{
    __shared__ float t[32][33];
    const int b  = blockIdx.z;
    const int c0 = blockIdx.x * 32;
    const int h0 = blockIdx.y * 32;
    const int cnt = g_cnt[b];
    if (c0 >= ((cnt + 127) & ~127)) return;   // beyond x2p pad128 region
    const int tid = threadIdx.x;
    const int tx = tid & 31, ty = tid >> 5;
    #pragma unroll
    for (int i = 0; i < 4; i++) {
        int cc = c0 + ty + i * 8;
        int j = g_jidx[b][cc < cnt ? cc : cnt - 1];   // clamp: finite fill
        t[ty + i * 8][tx] = X2[((size_t)b * LL + j) * HH + h0 + tx];
    }
    __syncthreads();

    // vtp: rows = h, k = c (fp16) — only the att-live pad64 region
    if (c0 < ((cnt + 63) & ~63)) {
        const int oy = tid >> 3;          // h local
        const int ox = (tid & 7) * 4;     // c local
        __half2 p01 = __float22half2_rn(make_float2(t[ox][oy],   t[ox+1][oy]));
        __half2 p23 = __float22half2_rn(make_float2(t[ox+2][oy], t[ox+3][oy]));
        const size_t row = (size_t)b * HH + h0 + oy;
        const int chunk = blockIdx.x >> 1;
        uint32_t* d = (uint32_t*)g_vtp + (row * KVS + chunk) * 32
                    + (blockIdx.x & 1) * 16 + (ox >> 1);
        *(uint2*)d = make_uint2(*reinterpret_cast<uint32_t*>(&p01),
                                *reinterpret_cast<uint32_t*>(&p23));
    }

    // x2p: rows = c, k = h (hi/lo bf16) — full pad128 region for proj
    {
        const int cl = tid >> 3;          // c local 0..31
        const int hl = (tid & 7) * 4;     // h local 0,4,..28
        float4 v = make_float4(t[cl][hl], t[cl][hl+1], t[cl][hl+2], t[cl][hl+3]);
        uint32_t h0b, h1b, l0b, l1b;
        split4(v, h0b, h1b, l0b, l1b);
        const size_t row = (size_t)b * LL + c0 + cl;
        const int k = h0 + hl;            // h0 multiple of 32
        uint32_t* d = (uint32_t*)g_x2p + (row * KCP + (k >> 5)) * 32 + ((k & 31) >> 1);
        *(uint2*)d        = make_uint2(h0b, h1b);
        *(uint2*)(d + 16) = make_uint2(l0b, l1b);
    }
}

// ---------------------------------------------------------------------------
// GEMM kernels
// ---------------------------------------------------------------------------
__global__ __launch_bounds__(256, 3) void proj_gemm(const float* __restrict__ bias)
{
    extern __shared__ char smem[];
    const int z  = blockIdx.z;
    const int y  = blockIdx.y;
    const int m0 = y * 128;
    const int n0 = blockIdx.x * 64;
    const int tid = threadIdx.x;

    if (z == 1) {
        const int b   = y >> 3;
        if (((y & 7) * 128) >= g_cnt[b]) return;
    }
    const uint8_t* a_tsrc = (const uint8_t*)(z ? g_x2p : g_x1p)
        + ((size_t)(m0 + (tid >> 1)) * KCP) * 128 + (tid & 1) * 64;
    const uint8_t* Bp = (const uint8_t*)g_wp + (size_t)n0 * KCP * 128;

    float c[2][4][4];
    gemm_main3(a_tsrc, Bp, KCP, smem, c);

    __syncthreads();
    const int lane = tid & 31, wid = tid >> 5;
    const int wm = wid >> 1, wn = wid & 1;
    #pragma unroll
    for (int mi = 0; mi < 2; mi++) {
        #pragma unroll
        for (int ni = 0; ni < 4; ni++) {
            const int cc = wn * 32 + ni * 8 + 2 * (lane & 3);
            const int gc = n0 + cc;
            const float b0 = bias[gc], b1 = bias[gc + 1];
            #pragma unroll
            for (int hrow = 0; hrow < 2; hrow++) {
                const int r = wm * 32 + mi * 16 + (lane >> 2) + 8 * hrow;
                float v0 = fmaxf(c[mi][ni][2*hrow + 0] + b0, 0.f);
                float v1 = fmaxf(c[mi][ni][2*hrow + 1] + b1, 0.f);
                __nv_bfloat162 h = __floats2bfloat162_rn(v0, v1);
                float2 f = __bfloat1622float2(h);
                __nv_bfloat162 l = __floats2bfloat162_rn(v0 - f.x, v1 - f.y);
                uint32_t off = (uint32_t)(r * 256 + (cc >> 5) * 128 + (cc & 31) * 2);
                *(uint32_t*)(smem + off)      = *reinterpret_cast<uint32_t*>(&h);
                *(uint32_t*)(smem + off + 64) = *reinterpret_cast<uint32_t*>(&l);
            }
        }
    }
    __syncthreads();
    uint4* dst = (z ? g_ypp : g_xpp);
    const uint4* ssrc = (const uint4*)smem;
    #pragma unroll
    for (int i = 0; i < 8; i++) {
        int idx = i * 256 + tid;
        int r   = idx >> 4;
        int ci  = (idx >> 3) & 1;
        int seg = idx & 7;
        dst[((size_t)(m0 + r) * KCP + (n0 >> 5) + ci) * 8 + seg] = ssrc[idx];
    }
}

__global__ __launch_bounds__(256, 3) void scores_gemm()
{
    extern __shared__ char smem[];
    const int b  = blockIdx.z;
    const int m0 = blockIdx.y * 128;
    const int n0 = blockIdx.x * 64;
    if (n0 >= g_cnt[b]) return;
    const int tid = threadIdx.x;
    const uint8_t* a_tsrc = (const uint8_t*)g_xpp
        + ((size_t)(b * LL + m0 + (tid >> 1)) * KCP) * 128 + (tid & 1) * 64;
    const uint8_t* Bp = (const uint8_t*)g_ypp + (size_t)(b * LL + n0) * KCP * 128;

    float c[2][4][4];
    gemm_main3(a_tsrc, Bp, KCP, smem, c);

    const int lane = tid & 31, wid = tid >> 5;
    const int wm = wid >> 1, wn = wid & 1;
    float* C = g_sc + ((size_t)b * LL + m0) * LL + n0;
    #pragma unroll
    for (int mi = 0; mi < 2; mi++) {
        const int r0 = wm * 32 + mi * 16 + (lane >> 2);
        #pragma unroll
        for (int ni = 0; ni < 4; ni++) {
            const int cc = wn * 32 + ni * 8 + 2 * (lane & 3);
            *(float2*)(C + (size_t)r0 * LL + cc)       = make_float2(c[mi][ni][0], c[mi][ni][1]);
            *(float2*)(C + (size_t)(r0 + 8) * LL + cc) = make_float2(c[mi][ni][2], c[mi][ni][3]);
        }
    }
}

// softmax over compacted columns; loads and alpha-writes restricted to live region
__global__ __launch_bounds__(256) void softmax_pack()
{
    const int b = blockIdx.y, i = blockIdx.x, tid = threadIdx.x;
    const float* row = g_sc + ((size_t)b * LL + i) * LL;
    const int cnt = g_cnt[b];
    const int KCb = (cnt + 63) >> 6;

    const int j0 = tid * 4;
    float4 s = make_float4(0.f, 0.f, 0.f, 0.f);
    if (j0 < cnt) s = *(const float4*)(row + j0);
    float v[4];
    v[0] = (j0 + 0 < cnt) ? s.x : -INFINITY;
    v[1] = (j0 + 1 < cnt) ? s.y : -INFINITY;
    v[2] = (j0 + 2 < cnt) ? s.z : -INFINITY;
    v[3] = (j0 + 3 < cnt) ? s.w : -INFINITY;

    float mx = fmaxf(fmaxf(v[0], v[1]), fmaxf(v[2], v[3]));
    #pragma unroll
    for (int o = 16; o > 0; o >>= 1) mx = fmaxf(mx, __shfl_xor_sync(0xffffffffu, mx, o));

    __shared__ float red[8];
    if ((tid & 31) == 0) red[tid >> 5] = mx;
    __syncthreads();
    float bm = red[0];
    #pragma unroll
    for (int w = 1; w < 8; w++) bm = fmaxf(bm, red[w]);

    float e[4];
    float sum = 0.f;
    #pragma unroll
    for (int q = 0; q < 4; q++) { e[q] = expf(v[q] - bm); sum += e[q]; }
    #pragma unroll
    for (int o = 16; o > 0; o >>= 1) sum += __shfl_xor_sync(0xffffffffu, sum, o);

    __syncthreads();
    if ((tid & 31) == 0) red[tid >> 5] = sum;
    __syncthreads();
    float bs = 0.f;
    #pragma unroll
    for (int w = 0; w < 8; w++) bs += red[w];
    const float inv = 1.0f / bs;

    const int chunk = tid >> 4;
    if (chunk < KCb) {
        __half2 p01 = __float22half2_rn(make_float2(e[0]*inv, e[1]*inv));
        __half2 p23 = __float22half2_rn(make_float2(e[2]*inv, e[3]*inv));
        uint32_t* d = (uint32_t*)g_ap + (((size_t)b * LL + i) * KCS + chunk) * 32
                    + (tid & 15) * 2;
        *(uint2*)d = make_uint2(*reinterpret_cast<uint32_t*>(&p01),
                                *reinterpret_cast<uint32_t*>(&p23));
    }
}

// att with per-batch runtime K = ceil(cnt/64) chunks
__global__ __launch_bounds__(256, 3) void att_gemm(const float* __restrict__ X1,
                                                   float* __restrict__ OUT)
{
    extern __shared__ char smem[];
    const int b  = blockIdx.z;
    const int m0 = blockIdx.y * 128;
    const int n0 = blockIdx.x * 64;
    const int KCb = (g_cnt[b] + 63) >> 6;
    const uint8_t* Ap = (const uint8_t*)g_ap  + (size_t)(b * LL + m0) * KCS * 128;
    const uint8_t* Bp = (const uint8_t*)g_vtp + (size_t)(b * HH + n0) * KVS * 128;

    float c[2][4][4];
    gemm_main1(Ap, Bp, KCb, smem, c);

    const int lane = threadIdx.x & 31, wid = threadIdx.x >> 5;
    const int wm = wid >> 1, wn = wid & 1;
    #pragma unroll
    for (int mi = 0; mi < 2; mi++) {
        const int r0 = m0 + wm * 32 + mi * 16 + (lane >> 2);
        #pragma unroll
        for (int ni = 0; ni < 4; ni++) {
            const int cc = wn * 32 + ni * 8 + 2 * (lane & 3);
            #pragma unroll
            for (int hrow = 0; hrow < 2; hrow++) {
                const int gr = r0 + 8 * hrow;
                float2 a = make_float2(c[mi][ni][2*hrow + 0], c[mi][ni][2*hrow + 1]);
                const float* xp = X1  + ((size_t)b * LL + gr) * HH   + n0 + cc;
                float*       op = OUT + ((size_t)b * LL + gr) * OUTW + n0 + cc;
                float2 x = *(const float2*)xp;
                *(float2*)(op)          = x;
                *(float2*)(op + HH)     = a;
                *(float2*)(op + 2*HH)   = make_float2(x.x * a.x, x.y * a.y);
                *(float2*)(op + 3*HH)   = make_float2(x.x - a.x, x.y - a.y);
            }
        }
    }
}

// ---------------------------------------------------------------------------
extern "C" void kernel_launch(void* const* d_in, const int* in_sizes, int n_in,
                              void* d_out, int out_size)
{
    (void)in_sizes; (void)n_in; (void)out_size;
    const float* x1   = (const float*)d_in[0];
    const float* x2   = (const float*)d_in[1];
    const int*   x2m  = (const int*)d_in[3];
    const float* W    = (const float*)d_in[4];
    const float* bias = (const float*)d_in[5];
    float*       out  = (float*)d_out;

    cudaFuncSetAttribute(proj_gemm,   cudaFuncAttributeMaxDynamicSharedMemorySize, SMEM_BYTES);
    cudaFuncSetAttribute(scores_gemm, cudaFuncAttributeMaxDynamicSharedMemorySize, SMEM_BYTES);
    cudaFuncSetAttribute(att_gemm,    cudaFuncAttributeMaxDynamicSharedMemorySize, SMEM_BYTES);

    prep_kernel<<<NB + PW_BLOCKS + PX1_BLOCKS, 256>>>(x2m, W, x1);  // 12880 blocks

    dim3 gT(LL/32, HH/32, NB);
    transpose_gather<<<gT, 256>>>(x2);

    dim3 gP(HH/64, (NB*LL)/128, 2);         // (12, 128, 2)
    proj_gemm<<<gP, 256, SMEM_BYTES>>>(bias);

    dim3 gS(LL/64, LL/128, NB);             // (16, 8, 16)
    scores_gemm<<<gS, 256, SMEM_BYTES>>>();

    dim3 gM(LL, NB);
    softmax_pack<<<gM, 256>>>();

    dim3 gA(HH/64, LL/128, NB);             // (12, 8, 16)
    att_gemm<<<gA, 256, SMEM_BYTES>>>(x1, out);
}